// round 13
// baseline (speedup 1.0000x reference)
#include <cuda_runtime.h>
#include <cuda_bf16.h>
#include <math.h>
#include <stdint.h>

#define B_      2
#define S_      2048
#define HIDDEN_ 4096
#define HD_     128
#define HQ_     32
#define HKV_    8
#define WINDOW_ 1024
#define CAP_    50.0f
#define EPS_    1e-5f

#define M_ROWS  (B_ * S_)   // 4096
#define NQKV    (HQ_ * HD_ + 2 * HKV_ * HD_)   // 6144

// ---------------- scratch (static device globals; no allocation) ----------------
__device__ __nv_bfloat16 g_xn[(size_t)M_ROWS * HIDDEN_];
__device__ __nv_bfloat16 g_qkv[(size_t)M_ROWS * NQKV];
__device__ __nv_bfloat16 g_ao[(size_t)M_ROWS * HQ_ * HD_];
__device__ __nv_bfloat16 g_wqkv[(size_t)HIDDEN_ * NQKV];      // [K][6144]
__device__ __nv_bfloat16 g_wo16[(size_t)HQ_ * HD_ * HIDDEN_]; // [K][N]

// ---------------- helpers ----------------
__device__ __forceinline__ uint32_t packbf(float a, float b) {
    __nv_bfloat162 t = __floats2bfloat162_rn(a, b);
    return *reinterpret_cast<uint32_t*>(&t);
}
__device__ __forceinline__ uint32_t smem_u32(const void* p) {
    return (uint32_t)__cvta_generic_to_shared(p);
}
#define CP_ASYNC16(dst, src) \
    asm volatile("cp.async.cg.shared.global [%0], [%1], 16;" :: "r"(dst), "l"(src))
#define CP_COMMIT() asm volatile("cp.async.commit_group;" ::: "memory")
#define CP_WAIT1()  asm volatile("cp.async.wait_group 1;" ::: "memory")

// ---------------- fp32 -> bf16 convert (Wo) ----------------
__global__ void f2bf_kernel(const float4* __restrict__ src,
                            __nv_bfloat162* __restrict__ dst, int n4) {
    int i = blockIdx.x * blockDim.x + threadIdx.x;
    if (i >= n4) return;
    float4 v = src[i];
    dst[2 * i]     = __floats2bfloat162_rn(v.x, v.y);
    dst[2 * i + 1] = __floats2bfloat162_rn(v.z, v.w);
}

// ---------------- pack Wq|Wk|Wv into [K][6144] bf16 ----------------
__global__ void pack_qkv_f2bf(const float* __restrict__ Wq,
                              const float* __restrict__ Wk,
                              const float* __restrict__ Wv,
                              __nv_bfloat162* __restrict__ dst) {
    int idx = blockIdx.x * blockDim.x + threadIdx.x;
    if (idx >= HIDDEN_ * (NQKV / 4)) return;
    int k  = idx / (NQKV / 4);
    int n4 = idx % (NQKV / 4);
    const float* src;
    if (n4 < 1024)      src = Wq + (size_t)k * 4096 + n4 * 4;
    else if (n4 < 1280) src = Wk + (size_t)k * 1024 + (n4 - 1024) * 4;
    else                src = Wv + (size_t)k * 1024 + (n4 - 1280) * 4;
    float4 v = *(const float4*)src;
    size_t d = (size_t)k * (NQKV / 2) + n4 * 2;
    dst[d]     = __floats2bfloat162_rn(v.x, v.y);
    dst[d + 1] = __floats2bfloat162_rn(v.z, v.w);
}

// ---------------- RMSNorm: one block per row, bf16 output ----------------
__global__ void rmsnorm_kernel(const float* __restrict__ x,
                               const float* __restrict__ gamma,
                               __nv_bfloat16* __restrict__ xn) {
    int row = blockIdx.x;
    const float4* xr = (const float4*)(x + (size_t)row * HIDDEN_);
    __nv_bfloat162* xnr = (__nv_bfloat162*)(xn + (size_t)row * HIDDEN_);
    const float4* g4 = (const float4*)gamma;
    int t = threadIdx.x;

    float ss = 0.f;
    float4 vals[4];
#pragma unroll
    for (int i = 0; i < 4; i++) {
        float4 v = xr[t + i * 256];
        vals[i] = v;
        ss += v.x * v.x + v.y * v.y + v.z * v.z + v.w * v.w;
    }
    __shared__ float red[256];
    red[t] = ss;
    __syncthreads();
    for (int s = 128; s > 0; s >>= 1) {
        if (t < s) red[t] += red[t + s];
        __syncthreads();
    }
    float rms = rsqrtf(red[0] / (float)HIDDEN_ + EPS_);
#pragma unroll
    for (int i = 0; i < 4; i++) {
        float4 v = vals[i];
        float4 g = g4[t + i * 256];
        int c = t + i * 256;
        xnr[2 * c]     = __floats2bfloat162_rn(v.x * rms * g.x, v.y * rms * g.y);
        xnr[2 * c + 1] = __floats2bfloat162_rn(v.z * rms * g.z, v.w * rms * g.w);
    }
}

// ---------------- BF16 mma.sync GEMM: 3-stage ring, 3 blocks/SM ----------------
// C[M,N] = A[M,K] @ B[K,N]. Block tile 128x128x32, 256 thr, warps 2(m) x 4(n).
#define TBK 32
#define AP  20           // A smem row stride in uint32 (80B) - conflict-free frags
#define BPB 136          // B smem row stride in bf16 (272B) - conflict-free ldmatrix
#define ABYT (128 * AP * 4)    // 10240 per stage
#define BBYT (TBK * BPB * 2)   // 8704 per stage
#define NSTG 3
#define GEMM_SMEM (NSTG * (ABYT + BBYT))   // 56832

template<int OUTBF>
__global__ void __launch_bounds__(256, 3)
bf16_gemm_kernel(const __nv_bfloat16* __restrict__ A,
                 const __nv_bfloat16* __restrict__ Bw,
                 const float* __restrict__ resid, void* __restrict__ Cout,
                 int N, int K) {
    extern __shared__ char smraw[];
    uint32_t sb = smem_u32(smraw);

    int tid  = threadIdx.x;
    int warp = tid >> 5;
    int lane = tid & 31;
    int gid  = lane >> 2;
    int l4   = lane & 3;
    int lmat = lane >> 3;
    int lrow = lane & 7;
    int wm = (warp & 1) * 64;
    int wn = (warp >> 1) * 32;

    size_t bm0 = (size_t)blockIdx.y * 128;
    int    bn0 = blockIdx.x * 128;

    int arow = tid >> 1;
    int aco  = (tid & 1) * 16;
    int brow = 2 * (tid >> 4) + (tid & 1);
    int bco  = ((tid >> 1) & 7) * 16;

    const __nv_bfloat16* ag = A + (bm0 + arow) * K + aco;
    const __nv_bfloat16* bg = Bw + (size_t)brow * N + bn0 + bco;
    uint32_t a_dst = sb + (uint32_t)(arow * AP + (aco >> 1)) * 4;        // stage 0 A dst
    uint32_t b_dst = sb + NSTG * ABYT + (uint32_t)(brow * BPB + bco) * 2; // stage 0 B dst

    // lane offsets within a stage
    uint32_t baddr[2];
#pragma unroll
    for (int p = 0; p < 2; p++)
        baddr[p] = 2u * (((lmat & 1) * 8 + lrow) * BPB
                         + wn + p * 16 + (lmat >> 1) * 8);
    uint32_t aaddr[4];
#pragma unroll
    for (int mt = 0; mt < 4; mt++)
        aaddr[mt] = (uint32_t)((wm + mt * 16 + (lmat & 1) * 8 + lrow) * AP) * 4
                    + (lmat >> 1) * 16;

    float acc[4][4][4];
#pragma unroll
    for (int mt = 0; mt < 4; mt++)
#pragma unroll
        for (int nt = 0; nt < 4; nt++)
#pragma unroll
            for (int r = 0; r < 4; r++) acc[mt][nt][r] = 0.f;

    int nk = K / TBK;

    auto stage = [&](int c) {
        int s = c % NSTG;
        uint32_t ad = a_dst + s * ABYT;
        uint32_t bd = b_dst + s * BBYT;
        const __nv_bfloat16* agn = ag + c * TBK;
        const __nv_bfloat16* bgn = bg + (size_t)c * TBK * N;
        CP_ASYNC16(ad, agn);
        CP_ASYNC16(ad + 16, agn + 8);
        CP_ASYNC16(bd, bgn);
        CP_ASYNC16(bd + 16, bgn + 8);
    };

    stage(0); CP_COMMIT();
    stage(1); CP_COMMIT();

    for (int kt = 0; kt < nk; kt++) {
        CP_WAIT1();
        __syncthreads();

        if (kt + 2 < nk) stage(kt + 2);
        CP_COMMIT();

        int s = kt % NSTG;
        uint32_t abase = sb + s * ABYT;
        uint32_t bbase = sb + NSTG * ABYT + s * BBYT;
#pragma unroll
        for (int kk = 0; kk < 2; kk++) {
            // B fragments for this kk (8 regs)
            uint32_t bf[2][4];
#pragma unroll
            for (int p = 0; p < 2; p++) {
                uint32_t ad = bbase + baddr[p] + kk * 16 * BPB * 2;
                asm volatile(
                    "ldmatrix.sync.aligned.m8n8.x4.trans.shared.b16 "
                    "{%0,%1,%2,%3}, [%4];"
                    : "=r"(bf[p][0]), "=r"(bf[p][1]),
                      "=r"(bf[p][2]), "=r"(bf[p][3])
                    : "r"(ad));
            }
            // per-mt: load A frag then immediately consume (low reg pressure)
#pragma unroll
            for (int mt = 0; mt < 4; mt++) {
                uint32_t a0, a1, a2, a3;
                uint32_t ad = abase + aaddr[mt] + kk * 32;
                asm volatile(
                    "ldmatrix.sync.aligned.m8n8.x4.shared.b16 "
                    "{%0,%1,%2,%3}, [%4];"
                    : "=r"(a0), "=r"(a1), "=r"(a2), "=r"(a3)
                    : "r"(ad));
#pragma unroll
                for (int nt = 0; nt < 4; nt++) {
                    uint32_t b0 = bf[nt >> 1][(nt & 1) * 2];
                    uint32_t b1 = bf[nt >> 1][(nt & 1) * 2 + 1];
                    asm volatile(
                        "mma.sync.aligned.m16n8k16.row.col.f32.bf16.bf16.f32 "
                        "{%0,%1,%2,%3}, {%4,%5,%6,%7}, {%8,%9}, {%0,%1,%2,%3};"
                        : "+f"(acc[mt][nt][0]), "+f"(acc[mt][nt][1]),
                          "+f"(acc[mt][nt][2]), "+f"(acc[mt][nt][3])
                        : "r"(a0), "r"(a1), "r"(a2), "r"(a3),
                          "r"(b0), "r"(b1));
                }
            }
        }
    }

    // epilogue
#pragma unroll
    for (int mt = 0; mt < 4; mt++) {
#pragma unroll
        for (int nt = 0; nt < 4; nt++) {
            int row = wm + mt * 16 + gid;
            int col = wn + nt * 8 + l4 * 2;
            size_t g0 = (bm0 + row) * N + bn0 + col;
            size_t g1 = g0 + (size_t)8 * N;
            if (OUTBF) {
                __nv_bfloat16* C16 = (__nv_bfloat16*)Cout;
                *(uint32_t*)(C16 + g0) = packbf(acc[mt][nt][0], acc[mt][nt][1]);
                *(uint32_t*)(C16 + g1) = packbf(acc[mt][nt][2], acc[mt][nt][3]);
            } else {
                float* C = (float*)Cout;
                float2 v0 = make_float2(acc[mt][nt][0], acc[mt][nt][1]);
                float2 v1 = make_float2(acc[mt][nt][2], acc[mt][nt][3]);
                float2 r0 = *(const float2*)(resid + g0);
                float2 r1 = *(const float2*)(resid + g1);
                v0.x += r0.x; v0.y += r0.y;
                v1.x += r1.x; v1.y += r1.y;
                *(float2*)(C + g0) = v0;
                *(float2*)(C + g1) = v1;
            }
        }
    }
}

// ---------------- RoPE in-place on bf16, rows of stride STRIDE, cols col0.. ----------
__global__ void rope_bf16_inplace(__nv_bfloat16* __restrict__ t,
                                  int n_heads, int stride, int col0, int total) {
    int idx = blockIdx.x * blockDim.x + threadIdx.x;
    if (idx >= total) return;
    int d   = idx & 63;
    int h   = (idx >> 6) % n_heads;
    int row = idx / (64 * n_heads);
    int s   = row % S_;

    float inv = expf(-((float)(2 * d) / (float)HD_) * logf(10000.0f));
    float ang = (float)s * inv;
    float c, sn;
    sincosf(ang, &sn, &c);

    size_t base = (size_t)row * stride + col0 + h * HD_;
    float v1 = __bfloat162float(t[base + d]);
    float v2 = __bfloat162float(t[base + d + 64]);
    t[base + d]      = __float2bfloat16(v1 * c - v2 * sn);
    t[base + d + 64] = __float2bfloat16(v2 * c + v1 * sn);
}

// ---------------- tensor-core flash attention (qkv packed, stride 6144) ----------
#define QT 64
#define KT 32
#define SPAD 136
#define ATTN_SMEM_BYTES ((QT * SPAD + 4 * KT * SPAD) * 2)   // 52224

__global__ void __launch_bounds__(128)
attn_mma_kernel(const __nv_bfloat16* __restrict__ qkv,
                __nv_bfloat16* __restrict__ o) {
    extern __shared__ __nv_bfloat16 smb[];
    __nv_bfloat16* Qs = smb;
    __nv_bfloat16* Ks = Qs + QT * SPAD;
    __nv_bfloat16* Vs = Ks + 2 * KT * SPAD;

    int tid  = threadIdx.x;
    int warp = tid >> 5;
    int lane = tid & 31;
    int gid  = lane >> 2;
    int l4   = lane & 3;
    int lrow = lane & 7;
    int lmat = lane >> 3;
    int i0 = blockIdx.x * QT;
    int h  = blockIdx.y;
    int b  = blockIdx.z;
    int g  = h >> 2;
    int wrow = warp * 16;

    {
        int r = tid >> 1;
        int c = (tid & 1) * 64;
        const uint4* src = (const uint4*)(qkv + ((size_t)(b * S_ + i0 + r)) * NQKV + h * HD_ + c);
        uint4* dst = (uint4*)&Qs[r * SPAD + c];
#pragma unroll
        for (int u = 0; u < 8; u++) dst[u] = src[u];
    }
    __syncthreads();

    uint32_t qsb = smem_u32(Qs);
    uint32_t a_q[8][4];
#pragma unroll
    for (int ks = 0; ks < 8; ks++) {
        int mrow = wrow + (lmat & 1) * 8 + lrow;
        int mcol = ks * 16 + (lmat >> 1) * 8;
        uint32_t ad = qsb + 2u * (mrow * SPAD + mcol);
        asm volatile("ldmatrix.sync.aligned.m8n8.x4.shared.b16 {%0,%1,%2,%3}, [%4];"
                     : "=r"(a_q[ks][0]), "=r"(a_q[ks][1]),
                       "=r"(a_q[ks][2]), "=r"(a_q[ks][3]) : "r"(ad));
    }

    uint32_t ksb = smem_u32(Ks);
    uint32_t vsb = smem_u32(Vs);

    float m0 = -1e30f, m1 = -1e30f, l0 = 0.f, l1 = 0.f;
    float oa[16][4];
#pragma unroll
    for (int nt = 0; nt < 16; nt++)
#pragma unroll
        for (int r = 0; r < 4; r++) oa[nt][r] = 0.f;

    int irow0 = i0 + wrow + gid;
    int irow1 = irow0 + 8;
    int iwmax = i0 + wrow + 15;
    int iwmin = i0 + wrow;

    int jstart = max(0, i0 - (WINDOW_ - 1)) & ~(KT - 1);
    int iend   = i0 + QT - 1;
    const float scale = 0.08838834764831845f;

    const __nv_bfloat16* kb = qkv + (size_t)b * S_ * NQKV + HQ_ * HD_ + g * HD_;
    const __nv_bfloat16* vb = kb + HKV_ * HD_;

    int sr = tid >> 2;
    int sc = (tid & 3) * 32;
    uint32_t kdst0 = ksb + 2u * (sr * SPAD + sc);
    uint32_t vdst0 = vsb + 2u * (sr * SPAD + sc);
    const uint32_t KVBUF = KT * SPAD * 2;

    {
        size_t off = (size_t)(jstart + sr) * NQKV + sc;
        const __nv_bfloat16* srk = kb + off;
        const __nv_bfloat16* srv = vb + off;
#pragma unroll
        for (int u = 0; u < 4; u++) {
            CP_ASYNC16(kdst0 + 16 * u, srk + 8 * u);
            CP_ASYNC16(vdst0 + 16 * u, srv + 8 * u);
        }
    }
    CP_COMMIT();

    int bufi = 0;
    for (int t0 = jstart; t0 <= iend; t0 += KT, bufi ^= 1) {
        int t1 = t0 + KT;
        if (t1 <= iend) {
            uint32_t bo = (bufi ^ 1) * KVBUF;
            size_t off = (size_t)(t1 + sr) * NQKV + sc;
            const __nv_bfloat16* srk = kb + off;
            const __nv_bfloat16* srv = vb + off;
#pragma unroll
            for (int u = 0; u < 4; u++) {
                CP_ASYNC16(kdst0 + bo + 16 * u, srk + 8 * u);
                CP_ASYNC16(vdst0 + bo + 16 * u, srv + 8 * u);
            }
        }
        CP_COMMIT();
        CP_WAIT1();
        __syncthreads();

        uint32_t kbase = ksb + bufi * KVBUF;
        uint32_t vbase = vsb + bufi * KVBUF;

        bool live = (t0 <= iwmax) && (t0 + KT - 1 > iwmin - WINDOW_);
        if (live) {
            float s[4][4];
#pragma unroll
            for (int nt = 0; nt < 4; nt++)
#pragma unroll
                for (int r = 0; r < 4; r++) s[nt][r] = 0.f;

#pragma unroll
            for (int ks = 0; ks < 8; ks++) {
                uint32_t b0[4], b1[4];
#pragma unroll
                for (int p = 0; p < 2; p++) {
                    int mrow = p * 16 + (lmat & 1) * 8 + lrow;
                    int mcol = ks * 16 + (lmat >> 1) * 8;
                    uint32_t ad = kbase + 2u * (mrow * SPAD + mcol);
                    uint32_t r0, r1, r2, r3;
                    asm volatile("ldmatrix.sync.aligned.m8n8.x4.shared.b16 {%0,%1,%2,%3}, [%4];"
                                 : "=r"(r0), "=r"(r1), "=r"(r2), "=r"(r3) : "r"(ad));
                    b0[2 * p] = r0; b0[2 * p + 1] = r1;
                    b1[2 * p] = r2; b1[2 * p + 1] = r3;
                }
#pragma unroll
                for (int nt = 0; nt < 4; nt++) {
                    asm volatile(
                        "mma.sync.aligned.m16n8k16.row.col.f32.bf16.bf16.f32 "
                        "{%0,%1,%2,%3}, {%4,%5,%6,%7}, {%8,%9}, {%0,%1,%2,%3};"
                        : "+f"(s[nt][0]), "+f"(s[nt][1]),
                          "+f"(s[nt][2]), "+f"(s[nt][3])
                        : "r"(a_q[ks][0]), "r"(a_q[ks][1]),
                          "r"(a_q[ks][2]), "r"(a_q[ks][3]),
                          "r"(b0[nt]), "r"(b1[nt]));
                }
            }

            float mx0 = -1e30f, mx1 = -1e30f;
#pragma unroll
            for (int nt = 0; nt < 4; nt++) {
                int j0 = t0 + nt * 8 + 2 * l4;
#pragma unroll
                for (int e = 0; e < 4; e++) {
                    int jj = j0 + (e & 1);
                    int ii = (e < 2) ? irow0 : irow1;
                    float x = s[nt][e] * scale;
                    float e2 = __expf(x * (-2.0f / CAP_));
                    x = CAP_ * __fdividef(1.f - e2, 1.f + e2);
                    bool valid = (jj <= ii) && (jj > ii - WINDOW_);
                    x = valid ? x : -1e30f;
                    s[nt][e] = x;
                    if (e < 2) mx0 = fmaxf(mx0, x);
                    else       mx1 = fmaxf(mx1, x);
                }
            }
            mx0 = fmaxf(mx0, __shfl_xor_sync(0xffffffffu, mx0, 1));
            mx0 = fmaxf(mx0, __shfl_xor_sync(0xffffffffu, mx0, 2));
            mx1 = fmaxf(mx1, __shfl_xor_sync(0xffffffffu, mx1, 1));
            mx1 = fmaxf(mx1, __shfl_xor_sync(0xffffffffu, mx1, 2));

            float mn0 = fmaxf(m0, mx0), mn1 = fmaxf(m1, mx1);
            float c0 = __expf(m0 - mn0), c1 = __expf(m1 - mn1);
            m0 = mn0; m1 = mn1;

            float rs0 = 0.f, rs1 = 0.f;
#pragma unroll
            for (int nt = 0; nt < 4; nt++) {
#pragma unroll
                for (int e = 0; e < 4; e++) {
                    float p = __expf(s[nt][e] - ((e < 2) ? mn0 : mn1));
                    s[nt][e] = p;
                    if (e < 2) rs0 += p; else rs1 += p;
                }
            }
            rs0 += __shfl_xor_sync(0xffffffffu, rs0, 1);
            rs0 += __shfl_xor_sync(0xffffffffu, rs0, 2);
            rs1 += __shfl_xor_sync(0xffffffffu, rs1, 1);
            rs1 += __shfl_xor_sync(0xffffffffu, rs1, 2);
            l0 = l0 * c0 + rs0;
            l1 = l1 * c1 + rs1;

#pragma unroll
            for (int nt = 0; nt < 16; nt++) {
                oa[nt][0] *= c0; oa[nt][1] *= c0;
                oa[nt][2] *= c1; oa[nt][3] *= c1;
            }

            uint32_t ap[2][4];
#pragma unroll
            for (int kp = 0; kp < 2; kp++) {
                int nA = 2 * kp, nB = 2 * kp + 1;
                ap[kp][0] = packbf(s[nA][0], s[nA][1]);
                ap[kp][1] = packbf(s[nA][2], s[nA][3]);
                ap[kp][2] = packbf(s[nB][0], s[nB][1]);
                ap[kp][3] = packbf(s[nB][2], s[nB][3]);
            }

#pragma unroll
            for (int kp = 0; kp < 2; kp++) {
#pragma unroll
                for (int ndp = 0; ndp < 8; ndp++) {
                    int mrow = kp * 16 + (lmat & 1) * 8 + lrow;
                    int mcol = ndp * 16 + (lmat >> 1) * 8;
                    uint32_t ad = vbase + 2u * (mrow * SPAD + mcol);
                    uint32_t r0, r1, r2, r3;
                    asm volatile("ldmatrix.sync.aligned.m8n8.x4.trans.shared.b16 {%0,%1,%2,%3}, [%4];"
                                 : "=r"(r0), "=r"(r1), "=r"(r2), "=r"(r3) : "r"(ad));
                    asm volatile(
                        "mma.sync.aligned.m16n8k16.row.col.f32.bf16.bf16.f32 "
                        "{%0,%1,%2,%3}, {%4,%5,%6,%7}, {%8,%9}, {%0,%1,%2,%3};"
                        : "+f"(oa[2 * ndp][0]), "+f"(oa[2 * ndp][1]),
                          "+f"(oa[2 * ndp][2]), "+f"(oa[2 * ndp][3])
                        : "r"(ap[kp][0]), "r"(ap[kp][1]),
                          "r"(ap[kp][2]), "r"(ap[kp][3]),
                          "r"(r0), "r"(r1));
                    asm volatile(
                        "mma.sync.aligned.m16n8k16.row.col.f32.bf16.bf16.f32 "
                        "{%0,%1,%2,%3}, {%4,%5,%6,%7}, {%8,%9}, {%0,%1,%2,%3};"
                        : "+f"(oa[2 * ndp + 1][0]), "+f"(oa[2 * ndp + 1][1]),
                          "+f"(oa[2 * ndp + 1][2]), "+f"(oa[2 * ndp + 1][3])
                        : "r"(ap[kp][0]), "r"(ap[kp][1]),
                          "r"(ap[kp][2]), "r"(ap[kp][3]),
                          "r"(r2), "r"(r3));
                }
            }
        }
        __syncthreads();
    }

    float inv0 = 1.0f / l0;
    float inv1 = 1.0f / l1;
    __nv_bfloat16* ob0 = o + (((size_t)b * S_ + irow0) * HQ_ + h) * HD_;
    __nv_bfloat16* ob1 = o + (((size_t)b * S_ + irow1) * HQ_ + h) * HD_;
#pragma unroll
    for (int nt = 0; nt < 16; nt++) {
        int col = nt * 8 + 2 * l4;
        *(uint32_t*)(ob0 + col) = packbf(oa[nt][0] * inv0, oa[nt][1] * inv0);
        *(uint32_t*)(ob1 + col) = packbf(oa[nt][2] * inv1, oa[nt][3] * inv1);
    }
}

// ---------------- launch ----------------
extern "C" void kernel_launch(void* const* d_in, const int* in_sizes, int n_in,
                              void* d_out, int out_size) {
    const float* x     = (const float*)d_in[0];
    const float* gamma = (const float*)d_in[1];
    const float* Wq    = (const float*)d_in[2];
    const float* Wk    = (const float*)d_in[3];
    const float* Wv    = (const float*)d_in[4];
    const float* Wo    = (const float*)d_in[5];
    float* out = (float*)d_out;

    __nv_bfloat16 *xn, *qkv, *ao, *wqkv, *wo16;
    cudaGetSymbolAddress((void**)&xn, g_xn);
    cudaGetSymbolAddress((void**)&qkv, g_qkv);
    cudaGetSymbolAddress((void**)&ao, g_ao);
    cudaGetSymbolAddress((void**)&wqkv, g_wqkv);
    cudaGetSymbolAddress((void**)&wo16, g_wo16);

    cudaFuncSetAttribute(attn_mma_kernel,
                         cudaFuncAttributeMaxDynamicSharedMemorySize, ATTN_SMEM_BYTES);
    cudaFuncSetAttribute(bf16_gemm_kernel<1>,
                         cudaFuncAttributeMaxDynamicSharedMemorySize, GEMM_SMEM);
    cudaFuncSetAttribute(bf16_gemm_kernel<0>,
                         cudaFuncAttributeMaxDynamicSharedMemorySize, GEMM_SMEM);

    // 0) weight packing / conversion
    {
        int n4p = HIDDEN_ * (NQKV / 4);
        pack_qkv_f2bf<<<(n4p + 255) / 256, 256>>>(Wq, Wk, Wv, (__nv_bfloat162*)wqkv);
        int n4o = HQ_ * HD_ * HIDDEN_ / 4;
        f2bf_kernel<<<(n4o + 255) / 256, 256>>>((const float4*)Wo, (__nv_bfloat162*)wo16, n4o);
    }

    // 1) RMSNorm (bf16 out)
    rmsnorm_kernel<<<M_ROWS, 256>>>(x, gamma, xn);

    // 2) fused QKV projection -> [M][6144] bf16
    bf16_gemm_kernel<1><<<dim3(NQKV / 128, M_ROWS / 128), 256, GEMM_SMEM>>>(
        xn, wqkv, nullptr, qkv, NQKV, HIDDEN_);

    // 3) RoPE in-place on q (cols 0..4095) and k (cols 4096..5119)
    int tot_q = B_ * S_ * HQ_ * (HD_ / 2);
    rope_bf16_inplace<<<(tot_q + 255) / 256, 256>>>(qkv, HQ_, NQKV, 0, tot_q);
    int tot_k = B_ * S_ * HKV_ * (HD_ / 2);
    rope_bf16_inplace<<<(tot_k + 255) / 256, 256>>>(qkv, HKV_, NQKV, HQ_ * HD_, tot_k);

    // 4) tensor-core flash attention
    dim3 ga(S_ / QT, HQ_, B_);
    attn_mma_kernel<<<ga, 128, ATTN_SMEM_BYTES>>>(qkv, ao);

    // 5) output projection + fp32 residual
    bf16_gemm_kernel<0><<<dim3(HIDDEN_ / 128, M_ROWS / 128), 256, GEMM_SMEM>>>(
        ao, wo16, x, out, HIDDEN_, HQ_ * HD_);
}

// round 14
// speedup vs baseline: 1.4835x; 1.4835x over previous
#include <cuda_runtime.h>
#include <cuda_bf16.h>
#include <math.h>
#include <stdint.h>

#define B_      2
#define S_      2048
#define HIDDEN_ 4096
#define HD_     128
#define HQ_     32
#define HKV_    8
#define WINDOW_ 1024
#define CAP_    50.0f
#define EPS_    1e-5f

#define M_ROWS  (B_ * S_)   // 4096
#define NQKV    (HQ_ * HD_ + 2 * HKV_ * HD_)   // 6144

// ---------------- scratch (static device globals; no allocation) ----------------
__device__ __nv_bfloat16 g_xn[(size_t)M_ROWS * HIDDEN_];
__device__ __nv_bfloat16 g_qkv[(size_t)M_ROWS * NQKV];
__device__ __nv_bfloat16 g_ao[(size_t)M_ROWS * HQ_ * HD_];
__device__ __nv_bfloat16 g_wqkv[(size_t)HIDDEN_ * NQKV];      // [K][6144]
__device__ __nv_bfloat16 g_wo16[(size_t)HQ_ * HD_ * HIDDEN_]; // [K][N]

// ---------------- helpers ----------------
__device__ __forceinline__ uint32_t packbf(float a, float b) {
    __nv_bfloat162 t = __floats2bfloat162_rn(a, b);
    return *reinterpret_cast<uint32_t*>(&t);
}
__device__ __forceinline__ uint32_t smem_u32(const void* p) {
    return (uint32_t)__cvta_generic_to_shared(p);
}
#define CP_ASYNC16(dst, src) \
    asm volatile("cp.async.cg.shared.global [%0], [%1], 16;" :: "r"(dst), "l"(src))
#define CP_COMMIT() asm volatile("cp.async.commit_group;" ::: "memory")
#define CP_WAIT1()  asm volatile("cp.async.wait_group 1;" ::: "memory")

// ---------------- fp32 -> bf16 convert (Wo) ----------------
__global__ void f2bf_kernel(const float4* __restrict__ src,
                            __nv_bfloat162* __restrict__ dst, int n4) {
    int i = blockIdx.x * blockDim.x + threadIdx.x;
    if (i >= n4) return;
    float4 v = src[i];
    dst[2 * i]     = __floats2bfloat162_rn(v.x, v.y);
    dst[2 * i + 1] = __floats2bfloat162_rn(v.z, v.w);
}

// ---------------- pack Wq|Wk|Wv into [K][6144] bf16 ----------------
__global__ void pack_qkv_f2bf(const float* __restrict__ Wq,
                              const float* __restrict__ Wk,
                              const float* __restrict__ Wv,
                              __nv_bfloat162* __restrict__ dst) {
    int idx = blockIdx.x * blockDim.x + threadIdx.x;
    if (idx >= HIDDEN_ * (NQKV / 4)) return;
    int k  = idx / (NQKV / 4);
    int n4 = idx % (NQKV / 4);
    const float* src;
    if (n4 < 1024)      src = Wq + (size_t)k * 4096 + n4 * 4;
    else if (n4 < 1280) src = Wk + (size_t)k * 1024 + (n4 - 1024) * 4;
    else                src = Wv + (size_t)k * 1024 + (n4 - 1280) * 4;
    float4 v = *(const float4*)src;
    size_t d = (size_t)k * (NQKV / 2) + n4 * 2;
    dst[d]     = __floats2bfloat162_rn(v.x, v.y);
    dst[d + 1] = __floats2bfloat162_rn(v.z, v.w);
}

// ---------------- RMSNorm: one block per row, bf16 output ----------------
__global__ void rmsnorm_kernel(const float* __restrict__ x,
                               const float* __restrict__ gamma,
                               __nv_bfloat16* __restrict__ xn) {
    int row = blockIdx.x;
    const float4* xr = (const float4*)(x + (size_t)row * HIDDEN_);
    __nv_bfloat162* xnr = (__nv_bfloat162*)(xn + (size_t)row * HIDDEN_);
    const float4* g4 = (const float4*)gamma;
    int t = threadIdx.x;

    float ss = 0.f;
    float4 vals[4];
#pragma unroll
    for (int i = 0; i < 4; i++) {
        float4 v = xr[t + i * 256];
        vals[i] = v;
        ss += v.x * v.x + v.y * v.y + v.z * v.z + v.w * v.w;
    }
    __shared__ float red[256];
    red[t] = ss;
    __syncthreads();
    for (int s = 128; s > 0; s >>= 1) {
        if (t < s) red[t] += red[t + s];
        __syncthreads();
    }
    float rms = rsqrtf(red[0] / (float)HIDDEN_ + EPS_);
#pragma unroll
    for (int i = 0; i < 4; i++) {
        float4 v = vals[i];
        float4 g = g4[t + i * 256];
        int c = t + i * 256;
        xnr[2 * c]     = __floats2bfloat162_rn(v.x * rms * g.x, v.y * rms * g.y);
        xnr[2 * c + 1] = __floats2bfloat162_rn(v.z * rms * g.z, v.w * rms * g.w);
    }
}

// ---------------- BF16 mma.sync GEMM: 512 thr, 16 warps of 32x32 tiles ----------
// C[M,N] = A[M,K] @ B[K,N]. Block tile 128x128x32, 3-stage cp.async ring.
// Warp grid 4(m) x 4(n). acc = 32 regs/thread -> 2 blocks/SM (32 warps).
#define TBK 32
#define AP  20           // A smem row stride in uint32 (80B) - conflict-free frags
#define BPB 136          // B smem row stride in bf16 (272B) - conflict-free ldmatrix
#define ABYT (128 * AP * 4)    // 10240 per stage
#define BBYT (TBK * BPB * 2)   // 8704 per stage
#define NSTG 3
#define GEMM_SMEM (NSTG * (ABYT + BBYT))   // 56832

template<int OUTBF>
__global__ void __launch_bounds__(512, 2)
bf16_gemm_kernel(const __nv_bfloat16* __restrict__ A,
                 const __nv_bfloat16* __restrict__ Bw,
                 const float* __restrict__ resid, void* __restrict__ Cout,
                 int N, int K) {
    extern __shared__ char smraw[];
    uint32_t sb = smem_u32(smraw);

    int tid  = threadIdx.x;
    int warp = tid >> 5;
    int lane = tid & 31;
    int gid  = lane >> 2;
    int l4   = lane & 3;
    int lmat = lane >> 3;
    int lrow = lane & 7;
    int wm = (warp & 3) * 32;
    int wn = (warp >> 2) * 32;

    size_t bm0 = (size_t)blockIdx.y * 128;
    int    bn0 = blockIdx.x * 128;

    // staging: A thread -> row tid>>2, 16B at col (tid&3)*8
    //          B thread -> row tid>>4, 16B at col (tid&15)*8
    int arow = tid >> 2;
    int aco  = (tid & 3) * 8;
    int brow = tid >> 4;
    int bco  = (tid & 15) * 8;

    const __nv_bfloat16* ag = A + (bm0 + arow) * K + aco;
    const __nv_bfloat16* bg = Bw + (size_t)brow * N + bn0 + bco;
    uint32_t a_dst = sb + (uint32_t)(arow * AP + (aco >> 1)) * 4;
    uint32_t b_dst = sb + NSTG * ABYT + (uint32_t)(brow * BPB + bco) * 2;

    // lane offsets within a stage
    uint32_t baddr[2];
#pragma unroll
    for (int p = 0; p < 2; p++)
        baddr[p] = 2u * (((lmat & 1) * 8 + lrow) * BPB
                         + wn + p * 16 + (lmat >> 1) * 8);
    uint32_t aaddr[2];
#pragma unroll
    for (int mt = 0; mt < 2; mt++)
        aaddr[mt] = (uint32_t)((wm + mt * 16 + (lmat & 1) * 8 + lrow) * AP) * 4
                    + (lmat >> 1) * 16;

    float acc[2][4][4];
#pragma unroll
    for (int mt = 0; mt < 2; mt++)
#pragma unroll
        for (int nt = 0; nt < 4; nt++)
#pragma unroll
            for (int r = 0; r < 4; r++) acc[mt][nt][r] = 0.f;

    int nk = K / TBK;

    auto stage = [&](int c) {
        int s = c % NSTG;
        CP_ASYNC16(a_dst + s * ABYT, ag + c * TBK);
        CP_ASYNC16(b_dst + s * BBYT, bg + (size_t)c * TBK * N);
    };

    stage(0); CP_COMMIT();
    stage(1); CP_COMMIT();

    for (int kt = 0; kt < nk; kt++) {
        CP_WAIT1();
        __syncthreads();

        if (kt + 2 < nk) stage(kt + 2);
        CP_COMMIT();

        int s = kt % NSTG;
        uint32_t abase = sb + s * ABYT;
        uint32_t bbase = sb + NSTG * ABYT + s * BBYT;
#pragma unroll
        for (int kk = 0; kk < 2; kk++) {
            uint32_t bf[2][4];
#pragma unroll
            for (int p = 0; p < 2; p++) {
                uint32_t ad = bbase + baddr[p] + kk * 16 * BPB * 2;
                asm volatile(
                    "ldmatrix.sync.aligned.m8n8.x4.trans.shared.b16 "
                    "{%0,%1,%2,%3}, [%4];"
                    : "=r"(bf[p][0]), "=r"(bf[p][1]),
                      "=r"(bf[p][2]), "=r"(bf[p][3])
                    : "r"(ad));
            }
#pragma unroll
            for (int mt = 0; mt < 2; mt++) {
                uint32_t a0, a1, a2, a3;
                uint32_t ad = abase + aaddr[mt] + kk * 32;
                asm volatile(
                    "ldmatrix.sync.aligned.m8n8.x4.shared.b16 "
                    "{%0,%1,%2,%3}, [%4];"
                    : "=r"(a0), "=r"(a1), "=r"(a2), "=r"(a3)
                    : "r"(ad));
#pragma unroll
                for (int nt = 0; nt < 4; nt++) {
                    uint32_t b0 = bf[nt >> 1][(nt & 1) * 2];
                    uint32_t b1 = bf[nt >> 1][(nt & 1) * 2 + 1];
                    asm volatile(
                        "mma.sync.aligned.m16n8k16.row.col.f32.bf16.bf16.f32 "
                        "{%0,%1,%2,%3}, {%4,%5,%6,%7}, {%8,%9}, {%0,%1,%2,%3};"
                        : "+f"(acc[mt][nt][0]), "+f"(acc[mt][nt][1]),
                          "+f"(acc[mt][nt][2]), "+f"(acc[mt][nt][3])
                        : "r"(a0), "r"(a1), "r"(a2), "r"(a3),
                          "r"(b0), "r"(b1));
                }
            }
        }
    }

    // epilogue
#pragma unroll
    for (int mt = 0; mt < 2; mt++) {
#pragma unroll
        for (int nt = 0; nt < 4; nt++) {
            int row = wm + mt * 16 + gid;
            int col = wn + nt * 8 + l4 * 2;
            size_t g0 = (bm0 + row) * N + bn0 + col;
            size_t g1 = g0 + (size_t)8 * N;
            if (OUTBF) {
                __nv_bfloat16* C16 = (__nv_bfloat16*)Cout;
                *(uint32_t*)(C16 + g0) = packbf(acc[mt][nt][0], acc[mt][nt][1]);
                *(uint32_t*)(C16 + g1) = packbf(acc[mt][nt][2], acc[mt][nt][3]);
            } else {
                float* C = (float*)Cout;
                float2 v0 = make_float2(acc[mt][nt][0], acc[mt][nt][1]);
                float2 v1 = make_float2(acc[mt][nt][2], acc[mt][nt][3]);
                float2 r0 = *(const float2*)(resid + g0);
                float2 r1 = *(const float2*)(resid + g1);
                v0.x += r0.x; v0.y += r0.y;
                v1.x += r1.x; v1.y += r1.y;
                *(float2*)(C + g0) = v0;
                *(float2*)(C + g1) = v1;
            }
        }
    }
}

// ---------------- RoPE in-place on bf16, rows of stride STRIDE, cols col0.. ----------
__global__ void rope_bf16_inplace(__nv_bfloat16* __restrict__ t,
                                  int n_heads, int stride, int col0, int total) {
    int idx = blockIdx.x * blockDim.x + threadIdx.x;
    if (idx >= total) return;
    int d   = idx & 63;
    int h   = (idx >> 6) % n_heads;
    int row = idx / (64 * n_heads);
    int s   = row % S_;

    float inv = expf(-((float)(2 * d) / (float)HD_) * logf(10000.0f));
    float ang = (float)s * inv;
    float c, sn;
    sincosf(ang, &sn, &c);

    size_t base = (size_t)row * stride + col0 + h * HD_;
    float v1 = __bfloat162float(t[base + d]);
    float v2 = __bfloat162float(t[base + d + 64]);
    t[base + d]      = __float2bfloat16(v1 * c - v2 * sn);
    t[base + d + 64] = __float2bfloat16(v2 * c + v1 * sn);
}

// ---------------- tensor-core flash attention (qkv packed, stride 6144) ----------
#define QT 64
#define KT 32
#define SPAD 136
#define ATTN_SMEM_BYTES ((QT * SPAD + 4 * KT * SPAD) * 2)   // 52224

__global__ void __launch_bounds__(128)
attn_mma_kernel(const __nv_bfloat16* __restrict__ qkv,
                __nv_bfloat16* __restrict__ o) {
    extern __shared__ __nv_bfloat16 smb[];
    __nv_bfloat16* Qs = smb;
    __nv_bfloat16* Ks = Qs + QT * SPAD;
    __nv_bfloat16* Vs = Ks + 2 * KT * SPAD;

    int tid  = threadIdx.x;
    int warp = tid >> 5;
    int lane = tid & 31;
    int gid  = lane >> 2;
    int l4   = lane & 3;
    int lrow = lane & 7;
    int lmat = lane >> 3;
    int i0 = blockIdx.x * QT;
    int h  = blockIdx.y;
    int b  = blockIdx.z;
    int g  = h >> 2;
    int wrow = warp * 16;

    {
        int r = tid >> 1;
        int c = (tid & 1) * 64;
        const uint4* src = (const uint4*)(qkv + ((size_t)(b * S_ + i0 + r)) * NQKV + h * HD_ + c);
        uint4* dst = (uint4*)&Qs[r * SPAD + c];
#pragma unroll
        for (int u = 0; u < 8; u++) dst[u] = src[u];
    }
    __syncthreads();

    uint32_t qsb = smem_u32(Qs);
    uint32_t a_q[8][4];
#pragma unroll
    for (int ks = 0; ks < 8; ks++) {
        int mrow = wrow + (lmat & 1) * 8 + lrow;
        int mcol = ks * 16 + (lmat >> 1) * 8;
        uint32_t ad = qsb + 2u * (mrow * SPAD + mcol);
        asm volatile("ldmatrix.sync.aligned.m8n8.x4.shared.b16 {%0,%1,%2,%3}, [%4];"
                     : "=r"(a_q[ks][0]), "=r"(a_q[ks][1]),
                       "=r"(a_q[ks][2]), "=r"(a_q[ks][3]) : "r"(ad));
    }

    uint32_t ksb = smem_u32(Ks);
    uint32_t vsb = smem_u32(Vs);

    float m0 = -1e30f, m1 = -1e30f, l0 = 0.f, l1 = 0.f;
    float oa[16][4];
#pragma unroll
    for (int nt = 0; nt < 16; nt++)
#pragma unroll
        for (int r = 0; r < 4; r++) oa[nt][r] = 0.f;

    int irow0 = i0 + wrow + gid;
    int irow1 = irow0 + 8;
    int iwmax = i0 + wrow + 15;
    int iwmin = i0 + wrow;

    int jstart = max(0, i0 - (WINDOW_ - 1)) & ~(KT - 1);
    int iend   = i0 + QT - 1;
    const float scale = 0.08838834764831845f;

    const __nv_bfloat16* kb = qkv + (size_t)b * S_ * NQKV + HQ_ * HD_ + g * HD_;
    const __nv_bfloat16* vb = kb + HKV_ * HD_;

    int sr = tid >> 2;
    int sc = (tid & 3) * 32;
    uint32_t kdst0 = ksb + 2u * (sr * SPAD + sc);
    uint32_t vdst0 = vsb + 2u * (sr * SPAD + sc);
    const uint32_t KVBUF = KT * SPAD * 2;

    {
        size_t off = (size_t)(jstart + sr) * NQKV + sc;
        const __nv_bfloat16* srk = kb + off;
        const __nv_bfloat16* srv = vb + off;
#pragma unroll
        for (int u = 0; u < 4; u++) {
            CP_ASYNC16(kdst0 + 16 * u, srk + 8 * u);
            CP_ASYNC16(vdst0 + 16 * u, srv + 8 * u);
        }
    }
    CP_COMMIT();

    int bufi = 0;
    for (int t0 = jstart; t0 <= iend; t0 += KT, bufi ^= 1) {
        int t1 = t0 + KT;
        if (t1 <= iend) {
            uint32_t bo = (bufi ^ 1) * KVBUF;
            size_t off = (size_t)(t1 + sr) * NQKV + sc;
            const __nv_bfloat16* srk = kb + off;
            const __nv_bfloat16* srv = vb + off;
#pragma unroll
            for (int u = 0; u < 4; u++) {
                CP_ASYNC16(kdst0 + bo + 16 * u, srk + 8 * u);
                CP_ASYNC16(vdst0 + bo + 16 * u, srv + 8 * u);
            }
        }
        CP_COMMIT();
        CP_WAIT1();
        __syncthreads();

        uint32_t kbase = ksb + bufi * KVBUF;
        uint32_t vbase = vsb + bufi * KVBUF;

        bool live = (t0 <= iwmax) && (t0 + KT - 1 > iwmin - WINDOW_);
        if (live) {
            float s[4][4];
#pragma unroll
            for (int nt = 0; nt < 4; nt++)
#pragma unroll
                for (int r = 0; r < 4; r++) s[nt][r] = 0.f;

#pragma unroll
            for (int ks = 0; ks < 8; ks++) {
                uint32_t b0[4], b1[4];
#pragma unroll
                for (int p = 0; p < 2; p++) {
                    int mrow = p * 16 + (lmat & 1) * 8 + lrow;
                    int mcol = ks * 16 + (lmat >> 1) * 8;
                    uint32_t ad = kbase + 2u * (mrow * SPAD + mcol);
                    uint32_t r0, r1, r2, r3;
                    asm volatile("ldmatrix.sync.aligned.m8n8.x4.shared.b16 {%0,%1,%2,%3}, [%4];"
                                 : "=r"(r0), "=r"(r1), "=r"(r2), "=r"(r3) : "r"(ad));
                    b0[2 * p] = r0; b0[2 * p + 1] = r1;
                    b1[2 * p] = r2; b1[2 * p + 1] = r3;
                }
#pragma unroll
                for (int nt = 0; nt < 4; nt++) {
                    asm volatile(
                        "mma.sync.aligned.m16n8k16.row.col.f32.bf16.bf16.f32 "
                        "{%0,%1,%2,%3}, {%4,%5,%6,%7}, {%8,%9}, {%0,%1,%2,%3};"
                        : "+f"(s[nt][0]), "+f"(s[nt][1]),
                          "+f"(s[nt][2]), "+f"(s[nt][3])
                        : "r"(a_q[ks][0]), "r"(a_q[ks][1]),
                          "r"(a_q[ks][2]), "r"(a_q[ks][3]),
                          "r"(b0[nt]), "r"(b1[nt]));
                }
            }

            float mx0 = -1e30f, mx1 = -1e30f;
#pragma unroll
            for (int nt = 0; nt < 4; nt++) {
                int j0 = t0 + nt * 8 + 2 * l4;
#pragma unroll
                for (int e = 0; e < 4; e++) {
                    int jj = j0 + (e & 1);
                    int ii = (e < 2) ? irow0 : irow1;
                    float x = s[nt][e] * scale;
                    float e2 = __expf(x * (-2.0f / CAP_));
                    x = CAP_ * __fdividef(1.f - e2, 1.f + e2);
                    bool valid = (jj <= ii) && (jj > ii - WINDOW_);
                    x = valid ? x : -1e30f;
                    s[nt][e] = x;
                    if (e < 2) mx0 = fmaxf(mx0, x);
                    else       mx1 = fmaxf(mx1, x);
                }
            }
            mx0 = fmaxf(mx0, __shfl_xor_sync(0xffffffffu, mx0, 1));
            mx0 = fmaxf(mx0, __shfl_xor_sync(0xffffffffu, mx0, 2));
            mx1 = fmaxf(mx1, __shfl_xor_sync(0xffffffffu, mx1, 1));
            mx1 = fmaxf(mx1, __shfl_xor_sync(0xffffffffu, mx1, 2));

            float mn0 = fmaxf(m0, mx0), mn1 = fmaxf(m1, mx1);
            float c0 = __expf(m0 - mn0), c1 = __expf(m1 - mn1);
            m0 = mn0; m1 = mn1;

            float rs0 = 0.f, rs1 = 0.f;
#pragma unroll
            for (int nt = 0; nt < 4; nt++) {
#pragma unroll
                for (int e = 0; e < 4; e++) {
                    float p = __expf(s[nt][e] - ((e < 2) ? mn0 : mn1));
                    s[nt][e] = p;
                    if (e < 2) rs0 += p; else rs1 += p;
                }
            }
            rs0 += __shfl_xor_sync(0xffffffffu, rs0, 1);
            rs0 += __shfl_xor_sync(0xffffffffu, rs0, 2);
            rs1 += __shfl_xor_sync(0xffffffffu, rs1, 1);
            rs1 += __shfl_xor_sync(0xffffffffu, rs1, 2);
            l0 = l0 * c0 + rs0;
            l1 = l1 * c1 + rs1;

#pragma unroll
            for (int nt = 0; nt < 16; nt++) {
                oa[nt][0] *= c0; oa[nt][1] *= c0;
                oa[nt][2] *= c1; oa[nt][3] *= c1;
            }

            uint32_t ap[2][4];
#pragma unroll
            for (int kp = 0; kp < 2; kp++) {
                int nA = 2 * kp, nB = 2 * kp + 1;
                ap[kp][0] = packbf(s[nA][0], s[nA][1]);
                ap[kp][1] = packbf(s[nA][2], s[nA][3]);
                ap[kp][2] = packbf(s[nB][0], s[nB][1]);
                ap[kp][3] = packbf(s[nB][2], s[nB][3]);
            }

#pragma unroll
            for (int kp = 0; kp < 2; kp++) {
#pragma unroll
                for (int ndp = 0; ndp < 8; ndp++) {
                    int mrow = kp * 16 + (lmat & 1) * 8 + lrow;
                    int mcol = ndp * 16 + (lmat >> 1) * 8;
                    uint32_t ad = vbase + 2u * (mrow * SPAD + mcol);
                    uint32_t r0, r1, r2, r3;
                    asm volatile("ldmatrix.sync.aligned.m8n8.x4.trans.shared.b16 {%0,%1,%2,%3}, [%4];"
                                 : "=r"(r0), "=r"(r1), "=r"(r2), "=r"(r3) : "r"(ad));
                    asm volatile(
                        "mma.sync.aligned.m16n8k16.row.col.f32.bf16.bf16.f32 "
                        "{%0,%1,%2,%3}, {%4,%5,%6,%7}, {%8,%9}, {%0,%1,%2,%3};"
                        : "+f"(oa[2 * ndp][0]), "+f"(oa[2 * ndp][1]),
                          "+f"(oa[2 * ndp][2]), "+f"(oa[2 * ndp][3])
                        : "r"(ap[kp][0]), "r"(ap[kp][1]),
                          "r"(ap[kp][2]), "r"(ap[kp][3]),
                          "r"(r0), "r"(r1));
                    asm volatile(
                        "mma.sync.aligned.m16n8k16.row.col.f32.bf16.bf16.f32 "
                        "{%0,%1,%2,%3}, {%4,%5,%6,%7}, {%8,%9}, {%0,%1,%2,%3};"
                        : "+f"(oa[2 * ndp + 1][0]), "+f"(oa[2 * ndp + 1][1]),
                          "+f"(oa[2 * ndp + 1][2]), "+f"(oa[2 * ndp + 1][3])
                        : "r"(ap[kp][0]), "r"(ap[kp][1]),
                          "r"(ap[kp][2]), "r"(ap[kp][3]),
                          "r"(r2), "r"(r3));
                }
            }
        }
        __syncthreads();
    }

    float inv0 = 1.0f / l0;
    float inv1 = 1.0f / l1;
    __nv_bfloat16* ob0 = o + (((size_t)b * S_ + irow0) * HQ_ + h) * HD_;
    __nv_bfloat16* ob1 = o + (((size_t)b * S_ + irow1) * HQ_ + h) * HD_;
#pragma unroll
    for (int nt = 0; nt < 16; nt++) {
        int col = nt * 8 + 2 * l4;
        *(uint32_t*)(ob0 + col) = packbf(oa[nt][0] * inv0, oa[nt][1] * inv0);
        *(uint32_t*)(ob1 + col) = packbf(oa[nt][2] * inv1, oa[nt][3] * inv1);
    }
}

// ---------------- launch ----------------
extern "C" void kernel_launch(void* const* d_in, const int* in_sizes, int n_in,
                              void* d_out, int out_size) {
    const float* x     = (const float*)d_in[0];
    const float* gamma = (const float*)d_in[1];
    const float* Wq    = (const float*)d_in[2];
    const float* Wk    = (const float*)d_in[3];
    const float* Wv    = (const float*)d_in[4];
    const float* Wo    = (const float*)d_in[5];
    float* out = (float*)d_out;

    __nv_bfloat16 *xn, *qkv, *ao, *wqkv, *wo16;
    cudaGetSymbolAddress((void**)&xn, g_xn);
    cudaGetSymbolAddress((void**)&qkv, g_qkv);
    cudaGetSymbolAddress((void**)&ao, g_ao);
    cudaGetSymbolAddress((void**)&wqkv, g_wqkv);
    cudaGetSymbolAddress((void**)&wo16, g_wo16);

    cudaFuncSetAttribute(attn_mma_kernel,
                         cudaFuncAttributeMaxDynamicSharedMemorySize, ATTN_SMEM_BYTES);
    cudaFuncSetAttribute(bf16_gemm_kernel<1>,
                         cudaFuncAttributeMaxDynamicSharedMemorySize, GEMM_SMEM);
    cudaFuncSetAttribute(bf16_gemm_kernel<0>,
                         cudaFuncAttributeMaxDynamicSharedMemorySize, GEMM_SMEM);

    // 0) weight packing / conversion
    {
        int n4p = HIDDEN_ * (NQKV / 4);
        pack_qkv_f2bf<<<(n4p + 255) / 256, 256>>>(Wq, Wk, Wv, (__nv_bfloat162*)wqkv);
        int n4o = HQ_ * HD_ * HIDDEN_ / 4;
        f2bf_kernel<<<(n4o + 255) / 256, 256>>>((const float4*)Wo, (__nv_bfloat162*)wo16, n4o);
    }

    // 1) RMSNorm (bf16 out)
    rmsnorm_kernel<<<M_ROWS, 256>>>(x, gamma, xn);

    // 2) fused QKV projection -> [M][6144] bf16
    bf16_gemm_kernel<1><<<dim3(NQKV / 128, M_ROWS / 128), 512, GEMM_SMEM>>>(
        xn, wqkv, nullptr, qkv, NQKV, HIDDEN_);

    // 3) RoPE in-place on q (cols 0..4095) and k (cols 4096..5119)
    int tot_q = B_ * S_ * HQ_ * (HD_ / 2);
    rope_bf16_inplace<<<(tot_q + 255) / 256, 256>>>(qkv, HQ_, NQKV, 0, tot_q);
    int tot_k = B_ * S_ * HKV_ * (HD_ / 2);
    rope_bf16_inplace<<<(tot_k + 255) / 256, 256>>>(qkv, HKV_, NQKV, HQ_ * HD_, tot_k);

    // 4) tensor-core flash attention
    dim3 ga(S_ / QT, HQ_, B_);
    attn_mma_kernel<<<ga, 128, ATTN_SMEM_BYTES>>>(qkv, ao);

    // 5) output projection + fp32 residual
    bf16_gemm_kernel<0><<<dim3(HIDDEN_ / 128, M_ROWS / 128), 512, GEMM_SMEM>>>(
        ao, wo16, x, out, HIDDEN_, HQ_ * HD_);
}

// round 15
// speedup vs baseline: 1.4886x; 1.0034x over previous
#include <cuda_runtime.h>
#include <cuda_bf16.h>
#include <math.h>
#include <stdint.h>

#define B_      2
#define S_      2048
#define HIDDEN_ 4096
#define HD_     128
#define HQ_     32
#define HKV_    8
#define WINDOW_ 1024
#define CAP_    50.0f
#define EPS_    1e-5f

#define M_ROWS  (B_ * S_)   // 4096
#define NQKV    (HQ_ * HD_ + 2 * HKV_ * HD_)   // 6144

// ---------------- scratch (static device globals; no allocation) ----------------
__device__ __nv_bfloat16 g_xn[(size_t)M_ROWS * HIDDEN_];
__device__ __nv_bfloat16 g_qkv[(size_t)M_ROWS * NQKV];
__device__ __nv_bfloat16 g_ao[(size_t)M_ROWS * HQ_ * HD_];
__device__ __nv_bfloat16 g_wqkv[(size_t)HIDDEN_ * NQKV];      // [K][6144]
__device__ __nv_bfloat16 g_wo16[(size_t)HQ_ * HD_ * HIDDEN_]; // [K][N]

// ---------------- helpers ----------------
__device__ __forceinline__ uint32_t packbf(float a, float b) {
    __nv_bfloat162 t = __floats2bfloat162_rn(a, b);
    return *reinterpret_cast<uint32_t*>(&t);
}
__device__ __forceinline__ uint32_t smem_u32(const void* p) {
    return (uint32_t)__cvta_generic_to_shared(p);
}
#define CP_ASYNC16(dst, src) \
    asm volatile("cp.async.cg.shared.global [%0], [%1], 16;" :: "r"(dst), "l"(src))
#define CP_COMMIT() asm volatile("cp.async.commit_group;" ::: "memory")
#define CP_WAIT1()  asm volatile("cp.async.wait_group 1;" ::: "memory")

// ---------------- fp32 -> bf16 convert (Wo) ----------------
__global__ void f2bf_kernel(const float4* __restrict__ src,
                            __nv_bfloat162* __restrict__ dst, int n4) {
    int i = blockIdx.x * blockDim.x + threadIdx.x;
    if (i >= n4) return;
    float4 v = src[i];
    dst[2 * i]     = __floats2bfloat162_rn(v.x, v.y);
    dst[2 * i + 1] = __floats2bfloat162_rn(v.z, v.w);
}

// ---------------- pack Wq|Wk|Wv into [K][6144] bf16 ----------------
__global__ void pack_qkv_f2bf(const float* __restrict__ Wq,
                              const float* __restrict__ Wk,
                              const float* __restrict__ Wv,
                              __nv_bfloat162* __restrict__ dst) {
    int idx = blockIdx.x * blockDim.x + threadIdx.x;
    if (idx >= HIDDEN_ * (NQKV / 4)) return;
    int k  = idx / (NQKV / 4);
    int n4 = idx % (NQKV / 4);
    const float* src;
    if (n4 < 1024)      src = Wq + (size_t)k * 4096 + n4 * 4;
    else if (n4 < 1280) src = Wk + (size_t)k * 1024 + (n4 - 1024) * 4;
    else                src = Wv + (size_t)k * 1024 + (n4 - 1280) * 4;
    float4 v = *(const float4*)src;
    size_t d = (size_t)k * (NQKV / 2) + n4 * 2;
    dst[d]     = __floats2bfloat162_rn(v.x, v.y);
    dst[d + 1] = __floats2bfloat162_rn(v.z, v.w);
}

// ---------------- RMSNorm: one block per row, bf16 output ----------------
__global__ void rmsnorm_kernel(const float* __restrict__ x,
                               const float* __restrict__ gamma,
                               __nv_bfloat16* __restrict__ xn) {
    int row = blockIdx.x;
    const float4* xr = (const float4*)(x + (size_t)row * HIDDEN_);
    __nv_bfloat162* xnr = (__nv_bfloat162*)(xn + (size_t)row * HIDDEN_);
    const float4* g4 = (const float4*)gamma;
    int t = threadIdx.x;

    float ss = 0.f;
    float4 vals[4];
#pragma unroll
    for (int i = 0; i < 4; i++) {
        float4 v = xr[t + i * 256];
        vals[i] = v;
        ss += v.x * v.x + v.y * v.y + v.z * v.z + v.w * v.w;
    }
    __shared__ float red[256];
    red[t] = ss;
    __syncthreads();
    for (int s = 128; s > 0; s >>= 1) {
        if (t < s) red[t] += red[t + s];
        __syncthreads();
    }
    float rms = rsqrtf(red[0] / (float)HIDDEN_ + EPS_);
#pragma unroll
    for (int i = 0; i < 4; i++) {
        float4 v = vals[i];
        float4 g = g4[t + i * 256];
        int c = t + i * 256;
        xnr[2 * c]     = __floats2bfloat162_rn(v.x * rms * g.x, v.y * rms * g.y);
        xnr[2 * c + 1] = __floats2bfloat162_rn(v.z * rms * g.z, v.w * rms * g.w);
    }
}

// ---------------- BF16 mma.sync GEMM: 512 thr, 16 warps of 32x32 tiles ----------
#define TBK 32
#define AP  20
#define BPB 136
#define ABYT (128 * AP * 4)    // 10240 per stage
#define BBYT (TBK * BPB * 2)   // 8704 per stage
#define NSTG 3
#define GEMM_SMEM (NSTG * (ABYT + BBYT))   // 56832

template<int OUTBF>
__global__ void __launch_bounds__(512, 2)
bf16_gemm_kernel(const __nv_bfloat16* __restrict__ A,
                 const __nv_bfloat16* __restrict__ Bw,
                 const float* __restrict__ resid, void* __restrict__ Cout,
                 int N, int K) {
    extern __shared__ char smraw[];
    uint32_t sb = smem_u32(smraw);

    int tid  = threadIdx.x;
    int warp = tid >> 5;
    int lane = tid & 31;
    int gid  = lane >> 2;
    int l4   = lane & 3;
    int lmat = lane >> 3;
    int lrow = lane & 7;
    int wm = (warp & 3) * 32;
    int wn = (warp >> 2) * 32;

    size_t bm0 = (size_t)blockIdx.y * 128;
    int    bn0 = blockIdx.x * 128;

    int arow = tid >> 2;
    int aco  = (tid & 3) * 8;
    int brow = tid >> 4;
    int bco  = (tid & 15) * 8;

    const __nv_bfloat16* ag = A + (bm0 + arow) * K + aco;
    const __nv_bfloat16* bg = Bw + (size_t)brow * N + bn0 + bco;
    uint32_t a_dst = sb + (uint32_t)(arow * AP + (aco >> 1)) * 4;
    uint32_t b_dst = sb + NSTG * ABYT + (uint32_t)(brow * BPB + bco) * 2;

    uint32_t baddr[2];
#pragma unroll
    for (int p = 0; p < 2; p++)
        baddr[p] = 2u * (((lmat & 1) * 8 + lrow) * BPB
                         + wn + p * 16 + (lmat >> 1) * 8);
    uint32_t aaddr[2];
#pragma unroll
    for (int mt = 0; mt < 2; mt++)
        aaddr[mt] = (uint32_t)((wm + mt * 16 + (lmat & 1) * 8 + lrow) * AP) * 4
                    + (lmat >> 1) * 16;

    float acc[2][4][4];
#pragma unroll
    for (int mt = 0; mt < 2; mt++)
#pragma unroll
        for (int nt = 0; nt < 4; nt++)
#pragma unroll
            for (int r = 0; r < 4; r++) acc[mt][nt][r] = 0.f;

    int nk = K / TBK;

    auto stage = [&](int c) {
        int s = c % NSTG;
        CP_ASYNC16(a_dst + s * ABYT, ag + c * TBK);
        CP_ASYNC16(b_dst + s * BBYT, bg + (size_t)c * TBK * N);
    };

    stage(0); CP_COMMIT();
    stage(1); CP_COMMIT();

    for (int kt = 0; kt < nk; kt++) {
        CP_WAIT1();
        __syncthreads();

        if (kt + 2 < nk) stage(kt + 2);
        CP_COMMIT();

        int s = kt % NSTG;
        uint32_t abase = sb + s * ABYT;
        uint32_t bbase = sb + NSTG * ABYT + s * BBYT;
#pragma unroll
        for (int kk = 0; kk < 2; kk++) {
            uint32_t bf[2][4];
#pragma unroll
            for (int p = 0; p < 2; p++) {
                uint32_t ad = bbase + baddr[p] + kk * 16 * BPB * 2;
                asm volatile(
                    "ldmatrix.sync.aligned.m8n8.x4.trans.shared.b16 "
                    "{%0,%1,%2,%3}, [%4];"
                    : "=r"(bf[p][0]), "=r"(bf[p][1]),
                      "=r"(bf[p][2]), "=r"(bf[p][3])
                    : "r"(ad));
            }
#pragma unroll
            for (int mt = 0; mt < 2; mt++) {
                uint32_t a0, a1, a2, a3;
                uint32_t ad = abase + aaddr[mt] + kk * 32;
                asm volatile(
                    "ldmatrix.sync.aligned.m8n8.x4.shared.b16 "
                    "{%0,%1,%2,%3}, [%4];"
                    : "=r"(a0), "=r"(a1), "=r"(a2), "=r"(a3)
                    : "r"(ad));
#pragma unroll
                for (int nt = 0; nt < 4; nt++) {
                    uint32_t b0 = bf[nt >> 1][(nt & 1) * 2];
                    uint32_t b1 = bf[nt >> 1][(nt & 1) * 2 + 1];
                    asm volatile(
                        "mma.sync.aligned.m16n8k16.row.col.f32.bf16.bf16.f32 "
                        "{%0,%1,%2,%3}, {%4,%5,%6,%7}, {%8,%9}, {%0,%1,%2,%3};"
                        : "+f"(acc[mt][nt][0]), "+f"(acc[mt][nt][1]),
                          "+f"(acc[mt][nt][2]), "+f"(acc[mt][nt][3])
                        : "r"(a0), "r"(a1), "r"(a2), "r"(a3),
                          "r"(b0), "r"(b1));
                }
            }
        }
    }

    // epilogue
#pragma unroll
    for (int mt = 0; mt < 2; mt++) {
#pragma unroll
        for (int nt = 0; nt < 4; nt++) {
            int row = wm + mt * 16 + gid;
            int col = wn + nt * 8 + l4 * 2;
            size_t g0 = (bm0 + row) * N + bn0 + col;
            size_t g1 = g0 + (size_t)8 * N;
            if (OUTBF) {
                __nv_bfloat16* C16 = (__nv_bfloat16*)Cout;
                *(uint32_t*)(C16 + g0) = packbf(acc[mt][nt][0], acc[mt][nt][1]);
                *(uint32_t*)(C16 + g1) = packbf(acc[mt][nt][2], acc[mt][nt][3]);
            } else {
                float* C = (float*)Cout;
                float2 v0 = make_float2(acc[mt][nt][0], acc[mt][nt][1]);
                float2 v1 = make_float2(acc[mt][nt][2], acc[mt][nt][3]);
                float2 r0 = *(const float2*)(resid + g0);
                float2 r1 = *(const float2*)(resid + g1);
                v0.x += r0.x; v0.y += r0.y;
                v1.x += r1.x; v1.y += r1.y;
                *(float2*)(C + g0) = v0;
                *(float2*)(C + g1) = v1;
            }
        }
    }
}

// ---------------- RoPE in-place on bf16, rows of stride STRIDE, cols col0.. ----------
__global__ void rope_bf16_inplace(__nv_bfloat16* __restrict__ t,
                                  int n_heads, int stride, int col0, int total) {
    int idx = blockIdx.x * blockDim.x + threadIdx.x;
    if (idx >= total) return;
    int d   = idx & 63;
    int h   = (idx >> 6) % n_heads;
    int row = idx / (64 * n_heads);
    int s   = row % S_;

    float inv = expf(-((float)(2 * d) / (float)HD_) * logf(10000.0f));
    float ang = (float)s * inv;
    float c, sn;
    sincosf(ang, &sn, &c);

    size_t base = (size_t)row * stride + col0 + h * HD_;
    float v1 = __bfloat162float(t[base + d]);
    float v2 = __bfloat162float(t[base + d + 64]);
    t[base + d]      = __float2bfloat16(v1 * c - v2 * sn);
    t[base + d + 64] = __float2bfloat16(v2 * c + v1 * sn);
}

// ---------------- tensor-core flash attention, 4 blocks/SM ----------------
// Q frags reloaded from smem per tile (no persistent a_q cache) to fit
// 128 regs -> 4 resident blocks (16 warps/SM).
#define QT 64
#define KT 32
#define SPAD 136
#define ATTN_SMEM_BYTES ((QT * SPAD + 4 * KT * SPAD) * 2)   // 52224

__global__ void __launch_bounds__(128, 4)
attn_mma_kernel(const __nv_bfloat16* __restrict__ qkv,
                __nv_bfloat16* __restrict__ o) {
    extern __shared__ __nv_bfloat16 smb[];
    __nv_bfloat16* Qs = smb;
    __nv_bfloat16* Ks = Qs + QT * SPAD;
    __nv_bfloat16* Vs = Ks + 2 * KT * SPAD;

    int tid  = threadIdx.x;
    int warp = tid >> 5;
    int lane = tid & 31;
    int gid  = lane >> 2;
    int l4   = lane & 3;
    int lrow = lane & 7;
    int lmat = lane >> 3;
    int i0 = blockIdx.x * QT;
    int h  = blockIdx.y;
    int b  = blockIdx.z;
    int g  = h >> 2;
    int wrow = warp * 16;

    // stage Q tile 64x128 bf16
    {
        int r = tid >> 1;
        int c = (tid & 1) * 64;
        const uint4* src = (const uint4*)(qkv + ((size_t)(b * S_ + i0 + r)) * NQKV + h * HD_ + c);
        uint4* dst = (uint4*)&Qs[r * SPAD + c];
#pragma unroll
        for (int u = 0; u < 8; u++) dst[u] = src[u];
    }
    __syncthreads();

    uint32_t qsb = smem_u32(Qs);
    uint32_t ksb = smem_u32(Ks);
    uint32_t vsb = smem_u32(Vs);
    // per-warp Q frag base address (per ks step add 32 bytes)
    uint32_t qaddr = qsb + 2u * ((wrow + (lmat & 1) * 8 + lrow) * SPAD
                                 + (lmat >> 1) * 8);

    float m0 = -1e30f, m1 = -1e30f, l0 = 0.f, l1 = 0.f;
    float oa[16][4];
#pragma unroll
    for (int nt = 0; nt < 16; nt++)
#pragma unroll
        for (int r = 0; r < 4; r++) oa[nt][r] = 0.f;

    int irow0 = i0 + wrow + gid;
    int irow1 = irow0 + 8;
    int iwmax = i0 + wrow + 15;
    int iwmin = i0 + wrow;

    int jstart = max(0, i0 - (WINDOW_ - 1)) & ~(KT - 1);
    int iend   = i0 + QT - 1;
    const float scale = 0.08838834764831845f;

    const __nv_bfloat16* kb = qkv + (size_t)b * S_ * NQKV + HQ_ * HD_ + g * HD_;
    const __nv_bfloat16* vb = kb + HKV_ * HD_;

    int sr = tid >> 2;
    int sc = (tid & 3) * 32;
    uint32_t kdst0 = ksb + 2u * (sr * SPAD + sc);
    uint32_t vdst0 = vsb + 2u * (sr * SPAD + sc);
    const uint32_t KVBUF = KT * SPAD * 2;

    {
        size_t off = (size_t)(jstart + sr) * NQKV + sc;
        const __nv_bfloat16* srk = kb + off;
        const __nv_bfloat16* srv = vb + off;
#pragma unroll
        for (int u = 0; u < 4; u++) {
            CP_ASYNC16(kdst0 + 16 * u, srk + 8 * u);
            CP_ASYNC16(vdst0 + 16 * u, srv + 8 * u);
        }
    }
    CP_COMMIT();

    int bufi = 0;
    for (int t0 = jstart; t0 <= iend; t0 += KT, bufi ^= 1) {
        int t1 = t0 + KT;
        if (t1 <= iend) {
            uint32_t bo = (bufi ^ 1) * KVBUF;
            size_t off = (size_t)(t1 + sr) * NQKV + sc;
            const __nv_bfloat16* srk = kb + off;
            const __nv_bfloat16* srv = vb + off;
#pragma unroll
            for (int u = 0; u < 4; u++) {
                CP_ASYNC16(kdst0 + bo + 16 * u, srk + 8 * u);
                CP_ASYNC16(vdst0 + bo + 16 * u, srv + 8 * u);
            }
        }
        CP_COMMIT();
        CP_WAIT1();
        __syncthreads();

        uint32_t kbase = ksb + bufi * KVBUF;
        uint32_t vbase = vsb + bufi * KVBUF;

        bool live = (t0 <= iwmax) && (t0 + KT - 1 > iwmin - WINDOW_);
        if (live) {
            float s[4][4];
#pragma unroll
            for (int nt = 0; nt < 4; nt++)
#pragma unroll
                for (int r = 0; r < 4; r++) s[nt][r] = 0.f;

#pragma unroll
            for (int ks = 0; ks < 8; ks++) {
                // Q fragment for this k-step (from smem, not cached)
                uint32_t aq0, aq1, aq2, aq3;
                asm volatile("ldmatrix.sync.aligned.m8n8.x4.shared.b16 {%0,%1,%2,%3}, [%4];"
                             : "=r"(aq0), "=r"(aq1), "=r"(aq2), "=r"(aq3)
                             : "r"(qaddr + ks * 32));
                uint32_t b0[4], b1[4];
#pragma unroll
                for (int p = 0; p < 2; p++) {
                    int mrow = p * 16 + (lmat & 1) * 8 + lrow;
                    int mcol = ks * 16 + (lmat >> 1) * 8;
                    uint32_t ad = kbase + 2u * (mrow * SPAD + mcol);
                    uint32_t r0, r1, r2, r3;
                    asm volatile("ldmatrix.sync.aligned.m8n8.x4.shared.b16 {%0,%1,%2,%3}, [%4];"
                                 : "=r"(r0), "=r"(r1), "=r"(r2), "=r"(r3) : "r"(ad));
                    b0[2 * p] = r0; b0[2 * p + 1] = r1;
                    b1[2 * p] = r2; b1[2 * p + 1] = r3;
                }
#pragma unroll
                for (int nt = 0; nt < 4; nt++) {
                    asm volatile(
                        "mma.sync.aligned.m16n8k16.row.col.f32.bf16.bf16.f32 "
                        "{%0,%1,%2,%3}, {%4,%5,%6,%7}, {%8,%9}, {%0,%1,%2,%3};"
                        : "+f"(s[nt][0]), "+f"(s[nt][1]),
                          "+f"(s[nt][2]), "+f"(s[nt][3])
                        : "r"(aq0), "r"(aq1), "r"(aq2), "r"(aq3),
                          "r"(b0[nt]), "r"(b1[nt]));
                }
            }

            float mx0 = -1e30f, mx1 = -1e30f;
#pragma unroll
            for (int nt = 0; nt < 4; nt++) {
                int j0 = t0 + nt * 8 + 2 * l4;
#pragma unroll
                for (int e = 0; e < 4; e++) {
                    int jj = j0 + (e & 1);
                    int ii = (e < 2) ? irow0 : irow1;
                    float x = s[nt][e] * scale;
                    float e2 = __expf(x * (-2.0f / CAP_));
                    x = CAP_ * __fdividef(1.f - e2, 1.f + e2);
                    bool valid = (jj <= ii) && (jj > ii - WINDOW_);
                    x = valid ? x : -1e30f;
                    s[nt][e] = x;
                    if (e < 2) mx0 = fmaxf(mx0, x);
                    else       mx1 = fmaxf(mx1, x);
                }
            }
            mx0 = fmaxf(mx0, __shfl_xor_sync(0xffffffffu, mx0, 1));
            mx0 = fmaxf(mx0, __shfl_xor_sync(0xffffffffu, mx0, 2));
            mx1 = fmaxf(mx1, __shfl_xor_sync(0xffffffffu, mx1, 1));
            mx1 = fmaxf(mx1, __shfl_xor_sync(0xffffffffu, mx1, 2));

            float mn0 = fmaxf(m0, mx0), mn1 = fmaxf(m1, mx1);
            float c0 = __expf(m0 - mn0), c1 = __expf(m1 - mn1);
            m0 = mn0; m1 = mn1;

            float rs0 = 0.f, rs1 = 0.f;
#pragma unroll
            for (int nt = 0; nt < 4; nt++) {
#pragma unroll
                for (int e = 0; e < 4; e++) {
                    float p = __expf(s[nt][e] - ((e < 2) ? mn0 : mn1));
                    s[nt][e] = p;
                    if (e < 2) rs0 += p; else rs1 += p;
                }
            }
            rs0 += __shfl_xor_sync(0xffffffffu, rs0, 1);
            rs0 += __shfl_xor_sync(0xffffffffu, rs0, 2);
            rs1 += __shfl_xor_sync(0xffffffffu, rs1, 1);
            rs1 += __shfl_xor_sync(0xffffffffu, rs1, 2);
            l0 = l0 * c0 + rs0;
            l1 = l1 * c1 + rs1;

#pragma unroll
            for (int nt = 0; nt < 16; nt++) {
                oa[nt][0] *= c0; oa[nt][1] *= c0;
                oa[nt][2] *= c1; oa[nt][3] *= c1;
            }

            uint32_t ap[2][4];
#pragma unroll
            for (int kp = 0; kp < 2; kp++) {
                int nA = 2 * kp, nB = 2 * kp + 1;
                ap[kp][0] = packbf(s[nA][0], s[nA][1]);
                ap[kp][1] = packbf(s[nA][2], s[nA][3]);
                ap[kp][2] = packbf(s[nB][0], s[nB][1]);
                ap[kp][3] = packbf(s[nB][2], s[nB][3]);
            }

#pragma unroll
            for (int kp = 0; kp < 2; kp++) {
#pragma unroll
                for (int ndp = 0; ndp < 8; ndp++) {
                    int mrow = kp * 16 + (lmat & 1) * 8 + lrow;
                    int mcol = ndp * 16 + (lmat >> 1) * 8;
                    uint32_t ad = vbase + 2u * (mrow * SPAD + mcol);
                    uint32_t r0, r1, r2, r3;
                    asm volatile("ldmatrix.sync.aligned.m8n8.x4.trans.shared.b16 {%0,%1,%2,%3}, [%4];"
                                 : "=r"(r0), "=r"(r1), "=r"(r2), "=r"(r3) : "r"(ad));
                    asm volatile(
                        "mma.sync.aligned.m16n8k16.row.col.f32.bf16.bf16.f32 "
                        "{%0,%1,%2,%3}, {%4,%5,%6,%7}, {%8,%9}, {%0,%1,%2,%3};"
                        : "+f"(oa[2 * ndp][0]), "+f"(oa[2 * ndp][1]),
                          "+f"(oa[2 * ndp][2]), "+f"(oa[2 * ndp][3])
                        : "r"(ap[kp][0]), "r"(ap[kp][1]),
                          "r"(ap[kp][2]), "r"(ap[kp][3]),
                          "r"(r0), "r"(r1));
                    asm volatile(
                        "mma.sync.aligned.m16n8k16.row.col.f32.bf16.bf16.f32 "
                        "{%0,%1,%2,%3}, {%4,%5,%6,%7}, {%8,%9}, {%0,%1,%2,%3};"
                        : "+f"(oa[2 * ndp + 1][0]), "+f"(oa[2 * ndp + 1][1]),
                          "+f"(oa[2 * ndp + 1][2]), "+f"(oa[2 * ndp + 1][3])
                        : "r"(ap[kp][0]), "r"(ap[kp][1]),
                          "r"(ap[kp][2]), "r"(ap[kp][3]),
                          "r"(r2), "r"(r3));
                }
            }
        }
        __syncthreads();
    }

    float inv0 = 1.0f / l0;
    float inv1 = 1.0f / l1;
    __nv_bfloat16* ob0 = o + (((size_t)b * S_ + irow0) * HQ_ + h) * HD_;
    __nv_bfloat16* ob1 = o + (((size_t)b * S_ + irow1) * HQ_ + h) * HD_;
#pragma unroll
    for (int nt = 0; nt < 16; nt++) {
        int col = nt * 8 + 2 * l4;
        *(uint32_t*)(ob0 + col) = packbf(oa[nt][0] * inv0, oa[nt][1] * inv0);
        *(uint32_t*)(ob1 + col) = packbf(oa[nt][2] * inv1, oa[nt][3] * inv1);
    }
}

// ---------------- launch ----------------
extern "C" void kernel_launch(void* const* d_in, const int* in_sizes, int n_in,
                              void* d_out, int out_size) {
    const float* x     = (const float*)d_in[0];
    const float* gamma = (const float*)d_in[1];
    const float* Wq    = (const float*)d_in[2];
    const float* Wk    = (const float*)d_in[3];
    const float* Wv    = (const float*)d_in[4];
    const float* Wo    = (const float*)d_in[5];
    float* out = (float*)d_out;

    __nv_bfloat16 *xn, *qkv, *ao, *wqkv, *wo16;
    cudaGetSymbolAddress((void**)&xn, g_xn);
    cudaGetSymbolAddress((void**)&qkv, g_qkv);
    cudaGetSymbolAddress((void**)&ao, g_ao);
    cudaGetSymbolAddress((void**)&wqkv, g_wqkv);
    cudaGetSymbolAddress((void**)&wo16, g_wo16);

    cudaFuncSetAttribute(attn_mma_kernel,
                         cudaFuncAttributeMaxDynamicSharedMemorySize, ATTN_SMEM_BYTES);
    cudaFuncSetAttribute(bf16_gemm_kernel<1>,
                         cudaFuncAttributeMaxDynamicSharedMemorySize, GEMM_SMEM);
    cudaFuncSetAttribute(bf16_gemm_kernel<0>,
                         cudaFuncAttributeMaxDynamicSharedMemorySize, GEMM_SMEM);

    // 0) weight packing / conversion
    {
        int n4p = HIDDEN_ * (NQKV / 4);
        pack_qkv_f2bf<<<(n4p + 255) / 256, 256>>>(Wq, Wk, Wv, (__nv_bfloat162*)wqkv);
        int n4o = HQ_ * HD_ * HIDDEN_ / 4;
        f2bf_kernel<<<(n4o + 255) / 256, 256>>>((const float4*)Wo, (__nv_bfloat162*)wo16, n4o);
    }

    // 1) RMSNorm (bf16 out)
    rmsnorm_kernel<<<M_ROWS, 256>>>(x, gamma, xn);

    // 2) fused QKV projection -> [M][6144] bf16
    bf16_gemm_kernel<1><<<dim3(NQKV / 128, M_ROWS / 128), 512, GEMM_SMEM>>>(
        xn, wqkv, nullptr, qkv, NQKV, HIDDEN_);

    // 3) RoPE in-place on q (cols 0..4095) and k (cols 4096..5119)
    int tot_q = B_ * S_ * HQ_ * (HD_ / 2);
    rope_bf16_inplace<<<(tot_q + 255) / 256, 256>>>(qkv, HQ_, NQKV, 0, tot_q);
    int tot_k = B_ * S_ * HKV_ * (HD_ / 2);
    rope_bf16_inplace<<<(tot_k + 255) / 256, 256>>>(qkv, HKV_, NQKV, HQ_ * HD_, tot_k);

    // 4) tensor-core flash attention
    dim3 ga(S_ / QT, HQ_, B_);
    attn_mma_kernel<<<ga, 128, ATTN_SMEM_BYTES>>>(qkv, ao);

    // 5) output projection + fp32 residual
    bf16_gemm_kernel<0><<<dim3(HIDDEN_ / 128, M_ROWS / 128), 512, GEMM_SMEM>>>(
        ao, wo16, x, out, HIDDEN_, HQ_ * HD_);
}

// round 16
// speedup vs baseline: 1.5199x; 1.0210x over previous
#include <cuda_runtime.h>
#include <cuda_bf16.h>
#include <math.h>
#include <stdint.h>

#define B_      2
#define S_      2048
#define HIDDEN_ 4096
#define HD_     128
#define HQ_     32
#define HKV_    8
#define WINDOW_ 1024
#define CAP_    50.0f
#define EPS_    1e-5f

#define M_ROWS  (B_ * S_)   // 4096
#define NQKV    (HQ_ * HD_ + 2 * HKV_ * HD_)   // 6144

// ---------------- scratch (static device globals; no allocation) ----------------
__device__ __nv_bfloat16 g_xn[(size_t)M_ROWS * HIDDEN_];
__device__ __nv_bfloat16 g_qkv[(size_t)M_ROWS * NQKV];
__device__ __nv_bfloat16 g_ao[(size_t)M_ROWS * HQ_ * HD_];
__device__ __nv_bfloat16 g_wqkv[(size_t)HIDDEN_ * NQKV];      // [K][6144]
__device__ __nv_bfloat16 g_wo16[(size_t)HQ_ * HD_ * HIDDEN_]; // [K][N]

// ---------------- helpers ----------------
__device__ __forceinline__ uint32_t packbf(float a, float b) {
    __nv_bfloat162 t = __floats2bfloat162_rn(a, b);
    return *reinterpret_cast<uint32_t*>(&t);
}
__device__ __forceinline__ uint32_t smem_u32(const void* p) {
    return (uint32_t)__cvta_generic_to_shared(p);
}
#define CP_ASYNC16(dst, src) \
    asm volatile("cp.async.cg.shared.global [%0], [%1], 16;" :: "r"(dst), "l"(src))
#define CP_COMMIT() asm volatile("cp.async.commit_group;" ::: "memory")
#define CP_WAIT1()  asm volatile("cp.async.wait_group 1;" ::: "memory")

// ---------------- fp32 -> bf16 convert (Wo) ----------------
__global__ void f2bf_kernel(const float4* __restrict__ src,
                            __nv_bfloat162* __restrict__ dst, int n4) {
    int i = blockIdx.x * blockDim.x + threadIdx.x;
    if (i >= n4) return;
    float4 v = src[i];
    dst[2 * i]     = __floats2bfloat162_rn(v.x, v.y);
    dst[2 * i + 1] = __floats2bfloat162_rn(v.z, v.w);
}

// ---------------- pack Wq|Wk|Wv into [K][6144] bf16 ----------------
__global__ void pack_qkv_f2bf(const float* __restrict__ Wq,
                              const float* __restrict__ Wk,
                              const float* __restrict__ Wv,
                              __nv_bfloat162* __restrict__ dst) {
    int idx = blockIdx.x * blockDim.x + threadIdx.x;
    if (idx >= HIDDEN_ * (NQKV / 4)) return;
    int k  = idx / (NQKV / 4);
    int n4 = idx % (NQKV / 4);
    const float* src;
    if (n4 < 1024)      src = Wq + (size_t)k * 4096 + n4 * 4;
    else if (n4 < 1280) src = Wk + (size_t)k * 1024 + (n4 - 1024) * 4;
    else                src = Wv + (size_t)k * 1024 + (n4 - 1280) * 4;
    float4 v = *(const float4*)src;
    size_t d = (size_t)k * (NQKV / 2) + n4 * 2;
    dst[d]     = __floats2bfloat162_rn(v.x, v.y);
    dst[d + 1] = __floats2bfloat162_rn(v.z, v.w);
}

// ---------------- RMSNorm: one block per row, bf16 output ----------------
__global__ void rmsnorm_kernel(const float* __restrict__ x,
                               const float* __restrict__ gamma,
                               __nv_bfloat16* __restrict__ xn) {
    int row = blockIdx.x;
    const float4* xr = (const float4*)(x + (size_t)row * HIDDEN_);
    __nv_bfloat162* xnr = (__nv_bfloat162*)(xn + (size_t)row * HIDDEN_);
    const float4* g4 = (const float4*)gamma;
    int t = threadIdx.x;

    float ss = 0.f;
    float4 vals[4];
#pragma unroll
    for (int i = 0; i < 4; i++) {
        float4 v = xr[t + i * 256];
        vals[i] = v;
        ss += v.x * v.x + v.y * v.y + v.z * v.z + v.w * v.w;
    }
    __shared__ float red[256];
    red[t] = ss;
    __syncthreads();
    for (int s = 128; s > 0; s >>= 1) {
        if (t < s) red[t] += red[t + s];
        __syncthreads();
    }
    float rms = rsqrtf(red[0] / (float)HIDDEN_ + EPS_);
#pragma unroll
    for (int i = 0; i < 4; i++) {
        float4 v = vals[i];
        float4 g = g4[t + i * 256];
        int c = t + i * 256;
        xnr[2 * c]     = __floats2bfloat162_rn(v.x * rms * g.x, v.y * rms * g.y);
        xnr[2 * c + 1] = __floats2bfloat162_rn(v.z * rms * g.z, v.w * rms * g.w);
    }
}

// ---------------- BF16 mma.sync GEMM: 512 thr, 16 warps of 32x32 tiles ----------
#define TBK 32
#define AP  20
#define BPB 136
#define ABYT (128 * AP * 4)    // 10240 per stage
#define BBYT (TBK * BPB * 2)   // 8704 per stage
#define NSTG 3
#define GEMM_SMEM (NSTG * (ABYT + BBYT))   // 56832

template<int OUTBF>
__global__ void __launch_bounds__(512, 2)
bf16_gemm_kernel(const __nv_bfloat16* __restrict__ A,
                 const __nv_bfloat16* __restrict__ Bw,
                 const float* __restrict__ resid, void* __restrict__ Cout,
                 int N, int K) {
    extern __shared__ char smraw[];
    uint32_t sb = smem_u32(smraw);

    int tid  = threadIdx.x;
    int warp = tid >> 5;
    int lane = tid & 31;
    int gid  = lane >> 2;
    int l4   = lane & 3;
    int lmat = lane >> 3;
    int lrow = lane & 7;
    int wm = (warp & 3) * 32;
    int wn = (warp >> 2) * 32;

    size_t bm0 = (size_t)blockIdx.y * 128;
    int    bn0 = blockIdx.x * 128;

    int arow = tid >> 2;
    int aco  = (tid & 3) * 8;
    int brow = tid >> 4;
    int bco  = (tid & 15) * 8;

    const __nv_bfloat16* ag = A + (bm0 + arow) * K + aco;
    const __nv_bfloat16* bg = Bw + (size_t)brow * N + bn0 + bco;
    uint32_t a_dst = sb + (uint32_t)(arow * AP + (aco >> 1)) * 4;
    uint32_t b_dst = sb + NSTG * ABYT + (uint32_t)(brow * BPB + bco) * 2;

    uint32_t baddr[2];
#pragma unroll
    for (int p = 0; p < 2; p++)
        baddr[p] = 2u * (((lmat & 1) * 8 + lrow) * BPB
                         + wn + p * 16 + (lmat >> 1) * 8);
    uint32_t aaddr[2];
#pragma unroll
    for (int mt = 0; mt < 2; mt++)
        aaddr[mt] = (uint32_t)((wm + mt * 16 + (lmat & 1) * 8 + lrow) * AP) * 4
                    + (lmat >> 1) * 16;

    float acc[2][4][4];
#pragma unroll
    for (int mt = 0; mt < 2; mt++)
#pragma unroll
        for (int nt = 0; nt < 4; nt++)
#pragma unroll
            for (int r = 0; r < 4; r++) acc[mt][nt][r] = 0.f;

    int nk = K / TBK;

    auto stage = [&](int c) {
        int s = c % NSTG;
        CP_ASYNC16(a_dst + s * ABYT, ag + c * TBK);
        CP_ASYNC16(b_dst + s * BBYT, bg + (size_t)c * TBK * N);
    };

    stage(0); CP_COMMIT();
    stage(1); CP_COMMIT();

    for (int kt = 0; kt < nk; kt++) {
        CP_WAIT1();
        __syncthreads();

        if (kt + 2 < nk) stage(kt + 2);
        CP_COMMIT();

        int s = kt % NSTG;
        uint32_t abase = sb + s * ABYT;
        uint32_t bbase = sb + NSTG * ABYT + s * BBYT;
#pragma unroll
        for (int kk = 0; kk < 2; kk++) {
            uint32_t bf[2][4];
#pragma unroll
            for (int p = 0; p < 2; p++) {
                uint32_t ad = bbase + baddr[p] + kk * 16 * BPB * 2;
                asm volatile(
                    "ldmatrix.sync.aligned.m8n8.x4.trans.shared.b16 "
                    "{%0,%1,%2,%3}, [%4];"
                    : "=r"(bf[p][0]), "=r"(bf[p][1]),
                      "=r"(bf[p][2]), "=r"(bf[p][3])
                    : "r"(ad));
            }
#pragma unroll
            for (int mt = 0; mt < 2; mt++) {
                uint32_t a0, a1, a2, a3;
                uint32_t ad = abase + aaddr[mt] + kk * 32;
                asm volatile(
                    "ldmatrix.sync.aligned.m8n8.x4.shared.b16 "
                    "{%0,%1,%2,%3}, [%4];"
                    : "=r"(a0), "=r"(a1), "=r"(a2), "=r"(a3)
                    : "r"(ad));
#pragma unroll
                for (int nt = 0; nt < 4; nt++) {
                    uint32_t b0 = bf[nt >> 1][(nt & 1) * 2];
                    uint32_t b1 = bf[nt >> 1][(nt & 1) * 2 + 1];
                    asm volatile(
                        "mma.sync.aligned.m16n8k16.row.col.f32.bf16.bf16.f32 "
                        "{%0,%1,%2,%3}, {%4,%5,%6,%7}, {%8,%9}, {%0,%1,%2,%3};"
                        : "+f"(acc[mt][nt][0]), "+f"(acc[mt][nt][1]),
                          "+f"(acc[mt][nt][2]), "+f"(acc[mt][nt][3])
                        : "r"(a0), "r"(a1), "r"(a2), "r"(a3),
                          "r"(b0), "r"(b1));
                }
            }
        }
    }

    // epilogue
#pragma unroll
    for (int mt = 0; mt < 2; mt++) {
#pragma unroll
        for (int nt = 0; nt < 4; nt++) {
            int row = wm + mt * 16 + gid;
            int col = wn + nt * 8 + l4 * 2;
            size_t g0 = (bm0 + row) * N + bn0 + col;
            size_t g1 = g0 + (size_t)8 * N;
            if (OUTBF) {
                __nv_bfloat16* C16 = (__nv_bfloat16*)Cout;
                *(uint32_t*)(C16 + g0) = packbf(acc[mt][nt][0], acc[mt][nt][1]);
                *(uint32_t*)(C16 + g1) = packbf(acc[mt][nt][2], acc[mt][nt][3]);
            } else {
                float* C = (float*)Cout;
                float2 v0 = make_float2(acc[mt][nt][0], acc[mt][nt][1]);
                float2 v1 = make_float2(acc[mt][nt][2], acc[mt][nt][3]);
                float2 r0 = *(const float2*)(resid + g0);
                float2 r1 = *(const float2*)(resid + g1);
                v0.x += r0.x; v0.y += r0.y;
                v1.x += r1.x; v1.y += r1.y;
                *(float2*)(C + g0) = v0;
                *(float2*)(C + g1) = v1;
            }
        }
    }
}

// ---------------- RoPE in-place on bf16 (q and k fused) ----------------
// total = rotations for q (HQ heads) + k (HKV heads); layout stride NQKV.
#define ROPE_Q_TOT (B_ * S_ * HQ_ * (HD_ / 2))
#define ROPE_K_TOT (B_ * S_ * HKV_ * (HD_ / 2))

__global__ void rope_bf16_fused(__nv_bfloat16* __restrict__ t) {
    int idx = blockIdx.x * blockDim.x + threadIdx.x;
    int n_heads, col0;
    if (idx < ROPE_Q_TOT) {
        n_heads = HQ_; col0 = 0;
    } else {
        idx -= ROPE_Q_TOT;
        if (idx >= ROPE_K_TOT) return;
        n_heads = HKV_; col0 = HQ_ * HD_;
    }
    int d   = idx & 63;
    int h   = (idx >> 6) % n_heads;
    int row = idx / (64 * n_heads);
    int s   = row % S_;

    float inv = expf(-((float)(2 * d) / (float)HD_) * logf(10000.0f));
    float ang = (float)s * inv;
    float c, sn;
    sincosf(ang, &sn, &c);

    size_t base = (size_t)row * NQKV + col0 + h * HD_;
    float v1 = __bfloat162float(t[base + d]);
    float v2 = __bfloat162float(t[base + d + 64]);
    t[base + d]      = __float2bfloat16(v1 * c - v2 * sn);
    t[base + d + 64] = __float2bfloat16(v2 * c + v1 * sn);
}

// ---------------- tensor-core flash attention, QT=128 (256 thr, 8 warps) --------
// Each staged K/V tile serves 128 queries (2x amortization vs QT=64).
#define QT 128
#define KT 32
#define SPAD 136
// Qs[QT*SPAD] + Ks[2][KT*SPAD] + Vs[2][KT*SPAD]
#define ATTN_SMEM_BYTES ((QT * SPAD + 4 * KT * SPAD) * 2)   // 69632

__global__ void __launch_bounds__(256, 2)
attn_mma_kernel(const __nv_bfloat16* __restrict__ qkv,
                __nv_bfloat16* __restrict__ o) {
    extern __shared__ __nv_bfloat16 smb[];
    __nv_bfloat16* Qs = smb;
    __nv_bfloat16* Ks = Qs + QT * SPAD;
    __nv_bfloat16* Vs = Ks + 2 * KT * SPAD;

    int tid  = threadIdx.x;
    int warp = tid >> 5;
    int lane = tid & 31;
    int gid  = lane >> 2;
    int l4   = lane & 3;
    int lrow = lane & 7;
    int lmat = lane >> 3;
    int i0 = blockIdx.x * QT;
    int h  = blockIdx.y;
    int b  = blockIdx.z;
    int g  = h >> 2;
    int wrow = warp * 16;

    // stage Q tile 128x128 bf16
    {
        int r = tid >> 1;                 // 0..127
        int c = (tid & 1) * 64;
        const uint4* src = (const uint4*)(qkv + ((size_t)(b * S_ + i0 + r)) * NQKV + h * HD_ + c);
        uint4* dst = (uint4*)&Qs[r * SPAD + c];
#pragma unroll
        for (int u = 0; u < 8; u++) dst[u] = src[u];
    }
    __syncthreads();

    uint32_t qsb = smem_u32(Qs);
    uint32_t ksb = smem_u32(Ks);
    uint32_t vsb = smem_u32(Vs);
    uint32_t qaddr = qsb + 2u * ((wrow + (lmat & 1) * 8 + lrow) * SPAD
                                 + (lmat >> 1) * 8);

    float m0 = -1e30f, m1 = -1e30f, l0 = 0.f, l1 = 0.f;
    float oa[16][4];
#pragma unroll
    for (int nt = 0; nt < 16; nt++)
#pragma unroll
        for (int r = 0; r < 4; r++) oa[nt][r] = 0.f;

    int irow0 = i0 + wrow + gid;
    int irow1 = irow0 + 8;
    int iwmax = i0 + wrow + 15;
    int iwmin = i0 + wrow;

    int jstart = max(0, i0 - (WINDOW_ - 1)) & ~(KT - 1);
    int iend   = i0 + QT - 1;
    const float scale = 0.08838834764831845f;

    const __nv_bfloat16* kb = qkv + (size_t)b * S_ * NQKV + HQ_ * HD_ + g * HD_;
    const __nv_bfloat16* vb = kb + HKV_ * HD_;

    // staging: 256 threads cover 32 rows x 128 cols, 32B (16 bf16) each
    int sr = tid >> 3;                    // 0..31
    int sc = (tid & 7) * 16;              // 0..112
    uint32_t kdst0 = ksb + 2u * (sr * SPAD + sc);
    uint32_t vdst0 = vsb + 2u * (sr * SPAD + sc);
    const uint32_t KVBUF = KT * SPAD * 2;

    {
        size_t off = (size_t)(jstart + sr) * NQKV + sc;
        const __nv_bfloat16* srk = kb + off;
        const __nv_bfloat16* srv = vb + off;
#pragma unroll
        for (int u = 0; u < 2; u++) {
            CP_ASYNC16(kdst0 + 16 * u, srk + 8 * u);
            CP_ASYNC16(vdst0 + 16 * u, srv + 8 * u);
        }
    }
    CP_COMMIT();

    int bufi = 0;
    for (int t0 = jstart; t0 <= iend; t0 += KT, bufi ^= 1) {
        int t1 = t0 + KT;
        if (t1 <= iend) {
            uint32_t bo = (bufi ^ 1) * KVBUF;
            size_t off = (size_t)(t1 + sr) * NQKV + sc;
            const __nv_bfloat16* srk = kb + off;
            const __nv_bfloat16* srv = vb + off;
#pragma unroll
            for (int u = 0; u < 2; u++) {
                CP_ASYNC16(kdst0 + bo + 16 * u, srk + 8 * u);
                CP_ASYNC16(vdst0 + bo + 16 * u, srv + 8 * u);
            }
        }
        CP_COMMIT();
        CP_WAIT1();
        __syncthreads();

        uint32_t kbase = ksb + bufi * KVBUF;
        uint32_t vbase = vsb + bufi * KVBUF;

        bool live = (t0 <= iwmax) && (t0 + KT - 1 > iwmin - WINDOW_);
        if (live) {
            float s[4][4];
#pragma unroll
            for (int nt = 0; nt < 4; nt++)
#pragma unroll
                for (int r = 0; r < 4; r++) s[nt][r] = 0.f;

#pragma unroll
            for (int ks = 0; ks < 8; ks++) {
                uint32_t aq0, aq1, aq2, aq3;
                asm volatile("ldmatrix.sync.aligned.m8n8.x4.shared.b16 {%0,%1,%2,%3}, [%4];"
                             : "=r"(aq0), "=r"(aq1), "=r"(aq2), "=r"(aq3)
                             : "r"(qaddr + ks * 32));
                uint32_t b0[4], b1[4];
#pragma unroll
                for (int p = 0; p < 2; p++) {
                    int mrow = p * 16 + (lmat & 1) * 8 + lrow;
                    int mcol = ks * 16 + (lmat >> 1) * 8;
                    uint32_t ad = kbase + 2u * (mrow * SPAD + mcol);
                    uint32_t r0, r1, r2, r3;
                    asm volatile("ldmatrix.sync.aligned.m8n8.x4.shared.b16 {%0,%1,%2,%3}, [%4];"
                                 : "=r"(r0), "=r"(r1), "=r"(r2), "=r"(r3) : "r"(ad));
                    b0[2 * p] = r0; b0[2 * p + 1] = r1;
                    b1[2 * p] = r2; b1[2 * p + 1] = r3;
                }
#pragma unroll
                for (int nt = 0; nt < 4; nt++) {
                    asm volatile(
                        "mma.sync.aligned.m16n8k16.row.col.f32.bf16.bf16.f32 "
                        "{%0,%1,%2,%3}, {%4,%5,%6,%7}, {%8,%9}, {%0,%1,%2,%3};"
                        : "+f"(s[nt][0]), "+f"(s[nt][1]),
                          "+f"(s[nt][2]), "+f"(s[nt][3])
                        : "r"(aq0), "r"(aq1), "r"(aq2), "r"(aq3),
                          "r"(b0[nt]), "r"(b1[nt]));
                }
            }

            float mx0 = -1e30f, mx1 = -1e30f;
#pragma unroll
            for (int nt = 0; nt < 4; nt++) {
                int j0 = t0 + nt * 8 + 2 * l4;
#pragma unroll
                for (int e = 0; e < 4; e++) {
                    int jj = j0 + (e & 1);
                    int ii = (e < 2) ? irow0 : irow1;
                    float x = s[nt][e] * scale;
                    float e2 = __expf(x * (-2.0f / CAP_));
                    x = CAP_ * __fdividef(1.f - e2, 1.f + e2);
                    bool valid = (jj <= ii) && (jj > ii - WINDOW_);
                    x = valid ? x : -1e30f;
                    s[nt][e] = x;
                    if (e < 2) mx0 = fmaxf(mx0, x);
                    else       mx1 = fmaxf(mx1, x);
                }
            }
            mx0 = fmaxf(mx0, __shfl_xor_sync(0xffffffffu, mx0, 1));
            mx0 = fmaxf(mx0, __shfl_xor_sync(0xffffffffu, mx0, 2));
            mx1 = fmaxf(mx1, __shfl_xor_sync(0xffffffffu, mx1, 1));
            mx1 = fmaxf(mx1, __shfl_xor_sync(0xffffffffu, mx1, 2));

            float mn0 = fmaxf(m0, mx0), mn1 = fmaxf(m1, mx1);
            float c0 = __expf(m0 - mn0), c1 = __expf(m1 - mn1);
            m0 = mn0; m1 = mn1;

            float rs0 = 0.f, rs1 = 0.f;
#pragma unroll
            for (int nt = 0; nt < 4; nt++) {
#pragma unroll
                for (int e = 0; e < 4; e++) {
                    float p = __expf(s[nt][e] - ((e < 2) ? mn0 : mn1));
                    s[nt][e] = p;
                    if (e < 2) rs0 += p; else rs1 += p;
                }
            }
            rs0 += __shfl_xor_sync(0xffffffffu, rs0, 1);
            rs0 += __shfl_xor_sync(0xffffffffu, rs0, 2);
            rs1 += __shfl_xor_sync(0xffffffffu, rs1, 1);
            rs1 += __shfl_xor_sync(0xffffffffu, rs1, 2);
            l0 = l0 * c0 + rs0;
            l1 = l1 * c1 + rs1;

#pragma unroll
            for (int nt = 0; nt < 16; nt++) {
                oa[nt][0] *= c0; oa[nt][1] *= c0;
                oa[nt][2] *= c1; oa[nt][3] *= c1;
            }

            uint32_t ap[2][4];
#pragma unroll
            for (int kp = 0; kp < 2; kp++) {
                int nA = 2 * kp, nB = 2 * kp + 1;
                ap[kp][0] = packbf(s[nA][0], s[nA][1]);
                ap[kp][1] = packbf(s[nA][2], s[nA][3]);
                ap[kp][2] = packbf(s[nB][0], s[nB][1]);
                ap[kp][3] = packbf(s[nB][2], s[nB][3]);
            }

#pragma unroll
            for (int kp = 0; kp < 2; kp++) {
#pragma unroll
                for (int ndp = 0; ndp < 8; ndp++) {
                    int mrow = kp * 16 + (lmat & 1) * 8 + lrow;
                    int mcol = ndp * 16 + (lmat >> 1) * 8;
                    uint32_t ad = vbase + 2u * (mrow * SPAD + mcol);
                    uint32_t r0, r1, r2, r3;
                    asm volatile("ldmatrix.sync.aligned.m8n8.x4.trans.shared.b16 {%0,%1,%2,%3}, [%4];"
                                 : "=r"(r0), "=r"(r1), "=r"(r2), "=r"(r3) : "r"(ad));
                    asm volatile(
                        "mma.sync.aligned.m16n8k16.row.col.f32.bf16.bf16.f32 "
                        "{%0,%1,%2,%3}, {%4,%5,%6,%7}, {%8,%9}, {%0,%1,%2,%3};"
                        : "+f"(oa[2 * ndp][0]), "+f"(oa[2 * ndp][1]),
                          "+f"(oa[2 * ndp][2]), "+f"(oa[2 * ndp][3])
                        : "r"(ap[kp][0]), "r"(ap[kp][1]),
                          "r"(ap[kp][2]), "r"(ap[kp][3]),
                          "r"(r0), "r"(r1));
                    asm volatile(
                        "mma.sync.aligned.m16n8k16.row.col.f32.bf16.bf16.f32 "
                        "{%0,%1,%2,%3}, {%4,%5,%6,%7}, {%8,%9}, {%0,%1,%2,%3};"
                        : "+f"(oa[2 * ndp + 1][0]), "+f"(oa[2 * ndp + 1][1]),
                          "+f"(oa[2 * ndp + 1][2]), "+f"(oa[2 * ndp + 1][3])
                        : "r"(ap[kp][0]), "r"(ap[kp][1]),
                          "r"(ap[kp][2]), "r"(ap[kp][3]),
                          "r"(r2), "r"(r3));
                }
            }
        }
        __syncthreads();
    }

    float inv0 = 1.0f / l0;
    float inv1 = 1.0f / l1;
    __nv_bfloat16* ob0 = o + (((size_t)b * S_ + irow0) * HQ_ + h) * HD_;
    __nv_bfloat16* ob1 = o + (((size_t)b * S_ + irow1) * HQ_ + h) * HD_;
#pragma unroll
    for (int nt = 0; nt < 16; nt++) {
        int col = nt * 8 + 2 * l4;
        *(uint32_t*)(ob0 + col) = packbf(oa[nt][0] * inv0, oa[nt][1] * inv0);
        *(uint32_t*)(ob1 + col) = packbf(oa[nt][2] * inv1, oa[nt][3] * inv1);
    }
}

// ---------------- launch ----------------
extern "C" void kernel_launch(void* const* d_in, const int* in_sizes, int n_in,
                              void* d_out, int out_size) {
    const float* x     = (const float*)d_in[0];
    const float* gamma = (const float*)d_in[1];
    const float* Wq    = (const float*)d_in[2];
    const float* Wk    = (const float*)d_in[3];
    const float* Wv    = (const float*)d_in[4];
    const float* Wo    = (const float*)d_in[5];
    float* out = (float*)d_out;

    __nv_bfloat16 *xn, *qkv, *ao, *wqkv, *wo16;
    cudaGetSymbolAddress((void**)&xn, g_xn);
    cudaGetSymbolAddress((void**)&qkv, g_qkv);
    cudaGetSymbolAddress((void**)&ao, g_ao);
    cudaGetSymbolAddress((void**)&wqkv, g_wqkv);
    cudaGetSymbolAddress((void**)&wo16, g_wo16);

    cudaFuncSetAttribute(attn_mma_kernel,
                         cudaFuncAttributeMaxDynamicSharedMemorySize, ATTN_SMEM_BYTES);
    cudaFuncSetAttribute(bf16_gemm_kernel<1>,
                         cudaFuncAttributeMaxDynamicSharedMemorySize, GEMM_SMEM);
    cudaFuncSetAttribute(bf16_gemm_kernel<0>,
                         cudaFuncAttributeMaxDynamicSharedMemorySize, GEMM_SMEM);

    // 0) weight packing / conversion
    {
        int n4p = HIDDEN_ * (NQKV / 4);
        pack_qkv_f2bf<<<(n4p + 255) / 256, 256>>>(Wq, Wk, Wv, (__nv_bfloat162*)wqkv);
        int n4o = HQ_ * HD_ * HIDDEN_ / 4;
        f2bf_kernel<<<(n4o + 255) / 256, 256>>>((const float4*)Wo, (__nv_bfloat162*)wo16, n4o);
    }

    // 1) RMSNorm (bf16 out)
    rmsnorm_kernel<<<M_ROWS, 256>>>(x, gamma, xn);

    // 2) fused QKV projection -> [M][6144] bf16
    bf16_gemm_kernel<1><<<dim3(NQKV / 128, M_ROWS / 128), 512, GEMM_SMEM>>>(
        xn, wqkv, nullptr, qkv, NQKV, HIDDEN_);

    // 3) RoPE in-place on q and k (single fused launch)
    int rope_tot = ROPE_Q_TOT + ROPE_K_TOT;
    rope_bf16_fused<<<(rope_tot + 255) / 256, 256>>>(qkv);

    // 4) tensor-core flash attention (QT=128)
    dim3 ga(S_ / QT, HQ_, B_);                 // (16, 32, 2)
    attn_mma_kernel<<<ga, 256, ATTN_SMEM_BYTES>>>(qkv, ao);

    // 5) output projection + fp32 residual
    bf16_gemm_kernel<0><<<dim3(HIDDEN_ / 128, M_ROWS / 128), 512, GEMM_SMEM>>>(
        ao, wo16, x, out, HIDDEN_, HQ_ * HD_);
}